// round 1
// baseline (speedup 1.0000x reference)
#include <cuda_runtime.h>
#include <math.h>

#define T_SEQ 2048
#define C_DIM 1024
#define NH    16
#define NKV   4
#define DHD   64
#define WINSZ 128

// ---------------- scratch (no allocations allowed) ----------------
__device__ float g_Q[T_SEQ * C_DIM];
__device__ float g_K[T_SEQ * NKV * DHD];
__device__ float g_V[T_SEQ * NKV * DHD];
__device__ float g_G[NH * T_SEQ];
__device__ float g_D[NH * T_SEQ];   // cumsum of log_sigmoid(gate)
__device__ float g_L[NH * T_SEQ];   // log_sigmoid(-gate)
__device__ float g_Y[T_SEQ * C_DIM];

__device__ __forceinline__ float neg_inf() { return __int_as_float(0xff800000); }

__device__ __forceinline__ float log_sigmoid_f(float x) {
    return fminf(x, 0.f) - log1pf(expf(-fabsf(x)));
}

// ---------------- generic GEMM: C[M,N] = A[M,K] @ B[K,N] ----------------
// 64x64 block tile, 16-wide K tile, 256 threads, 4x4 per thread.
// Requires M%64==0, N%64==0, K%16==0 (holds for all uses here).
__global__ __launch_bounds__(256) void gemm64(
    const float* __restrict__ A, const float* __restrict__ B,
    float* __restrict__ C, int M, int N, int K)
{
    __shared__ float As[64][17];
    __shared__ float Bs[16][65];
    int tid = threadIdx.x;
    int tx = tid & 15, ty = tid >> 4;
    int m0 = blockIdx.y * 64, n0 = blockIdx.x * 64;
    int arow = tid >> 2, akv = (tid & 3) * 4;
    int bkk  = tid >> 4, bcv = (tid & 15) * 4;
    float acc[4][4] = {};
    for (int k0 = 0; k0 < K; k0 += 16) {
        float4 a4 = *reinterpret_cast<const float4*>(A + (size_t)(m0 + arow) * K + k0 + akv);
        float4 b4 = *reinterpret_cast<const float4*>(B + (size_t)(k0 + bkk) * N + n0 + bcv);
        As[arow][akv + 0] = a4.x; As[arow][akv + 1] = a4.y;
        As[arow][akv + 2] = a4.z; As[arow][akv + 3] = a4.w;
        Bs[bkk][bcv + 0] = b4.x; Bs[bkk][bcv + 1] = b4.y;
        Bs[bkk][bcv + 2] = b4.z; Bs[bkk][bcv + 3] = b4.w;
        __syncthreads();
#pragma unroll
        for (int kk = 0; kk < 16; kk++) {
            float a[4], b[4];
#pragma unroll
            for (int i = 0; i < 4; i++) a[i] = As[ty * 4 + i][kk];
#pragma unroll
            for (int j = 0; j < 4; j++) b[j] = Bs[kk][tx * 4 + j];
#pragma unroll
            for (int i = 0; i < 4; i++)
#pragma unroll
                for (int j = 0; j < 4; j++) acc[i][j] += a[i] * b[j];
        }
        __syncthreads();
    }
#pragma unroll
    for (int i = 0; i < 4; i++) {
        float4 o = make_float4(acc[i][0], acc[i][1], acc[i][2], acc[i][3]);
        *reinterpret_cast<float4*>(C + (size_t)(m0 + ty * 4 + i) * N + n0 + tx * 4) = o;
    }
}

// ---------------- gate logits: G[h][t] = x[t]·Wg[:,h] + bg[h] ----------------
__global__ __launch_bounds__(256) void gate_kernel(
    const float* __restrict__ x, const float* __restrict__ Wg,
    const float* __restrict__ bg, float* __restrict__ G)
{
    __shared__ float xs[C_DIM];
    __shared__ float red[16][17];
    int t = blockIdx.x, tid = threadIdx.x;
    float4 v = *reinterpret_cast<const float4*>(x + (size_t)t * C_DIM + tid * 4);
    xs[tid * 4 + 0] = v.x; xs[tid * 4 + 1] = v.y;
    xs[tid * 4 + 2] = v.z; xs[tid * 4 + 3] = v.w;
    __syncthreads();
    int h = tid & 15, part = tid >> 4;
    float s = 0.f;
#pragma unroll 8
    for (int i = 0; i < 64; i++) {
        int c = part * 64 + i;
        s += xs[c] * Wg[c * NH + h];
    }
    red[part][h] = s;
    __syncthreads();
    if (tid < 16) {
        float acc = bg[tid];
#pragma unroll
        for (int p = 0; p < 16; p++) acc += red[p][tid];
        G[tid * T_SEQ + t] = acc;
    }
}

// ---------------- per-head inclusive scan of log_sigmoid(g); also L ----------------
__global__ __launch_bounds__(256) void scan_kernel(
    const float* __restrict__ G, float* __restrict__ D, float* __restrict__ L)
{
    int h = blockIdx.x, tid = threadIdx.x;
    const float* g = G + h * T_SEQ;
    float vals[8];
    float run = 0.f;
#pragma unroll
    for (int i = 0; i < 8; i++) {
        float gg = g[tid * 8 + i];
        run += log_sigmoid_f(gg);
        vals[i] = run;
        L[h * T_SEQ + tid * 8 + i] = log_sigmoid_f(-gg);
    }
    __shared__ float s[256];
    s[tid] = run;
    __syncthreads();
    for (int off = 1; off < 256; off <<= 1) {
        float v = 0.f;
        if (tid >= off) v = s[tid - off];
        __syncthreads();
        s[tid] += v;
        __syncthreads();
    }
    float excl = s[tid] - run;
#pragma unroll
    for (int i = 0; i < 8; i++) D[h * T_SEQ + tid * 8 + i] = vals[i] + excl;
}

// ---------------- RoPE (in place), heads = NH for Q, NKV for K ----------------
__global__ __launch_bounds__(256) void rope_kernel(float* __restrict__ P, int heads)
{
    int idx = blockIdx.x * blockDim.x + threadIdx.x;
    int total = T_SEQ * heads * 32;
    if (idx >= total) return;
    int d = idx & 31;
    int h = (idx >> 5) % heads;
    int t = idx / (heads * 32);
    // inv_freq = 10000^(-2d/64) = exp(-(2d/64)*ln(10000))
    float inv = expf(-(float)(2 * d) * (9.210340371976184f / 64.f));
    float theta = (float)t * inv;
    float sn, cs;
    sincosf(theta, &sn, &cs);
    float* p = P + (size_t)t * heads * DHD + h * DHD;
    float a = p[d], b = p[d + 32];
    p[d]      = a * cs - b * sn;
    p[d + 32] = b * cs + a * sn;
}

// ---------------- global gated-decay attention (writes Y) ----------------
// grid (T/64, H), 256 threads. Flash-style tiles with exact-zero decay skip.
__global__ __launch_bounds__(256) void global_attn(
    const float* __restrict__ Q, const float* __restrict__ K,
    const float* __restrict__ V, const float* __restrict__ D,
    const float* __restrict__ L, float* __restrict__ Y)
{
    extern __shared__ float sm[];
    float (*Qs)[65] = (float(*)[65])sm;
    float (*Ks)[65] = (float(*)[65])(sm + 64 * 65);
    float (*Vs)[65] = (float(*)[65])(sm + 2 * 64 * 65);
    float (*Ss)[65] = (float(*)[65])(sm + 3 * 64 * 65);
    float* Dq   = sm + 4 * 64 * 65;
    float* rowE = Dq + 64;
    float* Ds   = rowE + 64;
    float* Ls   = Ds + 64;
    float* colE = Ls + 64;

    int qt = blockIdx.x, h = blockIdx.y;
    int kvh = h >> 2;                      // n_rep = 4 (contiguous repeat)
    int tid = threadIdx.x, tx = tid & 15, ty = tid >> 4;
    int t0 = qt * 64;

    for (int f = tid; f < 64 * 16; f += 256) {
        int r = f >> 4, cv = (f & 15) * 4;
        float4 v = *reinterpret_cast<const float4*>(Q + (size_t)(t0 + r) * C_DIM + h * DHD + cv);
        Qs[r][cv + 0] = v.x; Qs[r][cv + 1] = v.y; Qs[r][cv + 2] = v.z; Qs[r][cv + 3] = v.w;
    }
    if (tid < 64) Dq[tid] = D[h * T_SEQ + t0 + tid];
    __syncthreads();
    float dq0 = Dq[0];
    if (tid < 64) rowE[tid] = expf(Dq[tid] - dq0);

    float acc[4][4] = {};
    for (int st = qt; st >= 0; st--) {
        int s0 = st * 64;
        if (st < qt) {
            // decay monotonically dies; below -88 the reference's own exp is 0
            float dend = D[h * T_SEQ + s0 + 63];
            if (dq0 - dend < -88.f) break;
        }
        __syncthreads();
        for (int f = tid; f < 64 * 16; f += 256) {
            int r = f >> 4, cv = (f & 15) * 4;
            float4 kk4 = *reinterpret_cast<const float4*>(K + (size_t)(s0 + r) * (NKV * DHD) + kvh * DHD + cv);
            Ks[r][cv + 0] = kk4.x; Ks[r][cv + 1] = kk4.y; Ks[r][cv + 2] = kk4.z; Ks[r][cv + 3] = kk4.w;
            float4 vv4 = *reinterpret_cast<const float4*>(V + (size_t)(s0 + r) * (NKV * DHD) + kvh * DHD + cv);
            Vs[r][cv + 0] = vv4.x; Vs[r][cv + 1] = vv4.y; Vs[r][cv + 2] = vv4.z; Vs[r][cv + 3] = vv4.w;
        }
        if (tid < 64) {
            float ds = D[h * T_SEQ + s0 + tid];
            float ls = L[h * T_SEQ + s0 + tid];
            Ds[tid] = ds; Ls[tid] = ls;
            colE[tid] = expf(dq0 - ds + ls);   // <= 1 for strictly-lower tiles
        }
        __syncthreads();

        float sc[4][4] = {};
#pragma unroll
        for (int kk = 0; kk < 64; kk++) {
            float a[4], b[4];
#pragma unroll
            for (int i = 0; i < 4; i++) a[i] = Qs[ty * 4 + i][kk];
#pragma unroll
            for (int j = 0; j < 4; j++) b[j] = Ks[tx * 4 + j][kk];
#pragma unroll
            for (int i = 0; i < 4; i++)
#pragma unroll
                for (int j = 0; j < 4; j++) sc[i][j] += a[i] * b[j];
        }
        if (st == qt) {
            // diagonal tile: direct exp per element (avoids inf*0 in factored form)
#pragma unroll
            for (int i = 0; i < 4; i++) {
                int ti = ty * 4 + i;
#pragma unroll
                for (int j = 0; j < 4; j++) {
                    int sj = tx * 4 + j;
                    float w = (sj <= ti) ? expf(Dq[ti] - Ds[sj] + Ls[sj]) : 0.f;
                    Ss[ti][sj] = sc[i][j] * w;
                }
            }
        } else {
#pragma unroll
            for (int i = 0; i < 4; i++) {
                float re = rowE[ty * 4 + i];
#pragma unroll
                for (int j = 0; j < 4; j++)
                    Ss[ty * 4 + i][tx * 4 + j] = sc[i][j] * (re * colE[tx * 4 + j]);
            }
        }
        __syncthreads();
#pragma unroll
        for (int kk = 0; kk < 64; kk++) {
            float p[4], vv[4];
#pragma unroll
            for (int i = 0; i < 4; i++) p[i] = Ss[ty * 4 + i][kk];
#pragma unroll
            for (int j = 0; j < 4; j++) vv[j] = Vs[kk][tx * 4 + j];
#pragma unroll
            for (int i = 0; i < 4; i++)
#pragma unroll
                for (int j = 0; j < 4; j++) acc[i][j] += p[i] * vv[j];
        }
    }
#pragma unroll
    for (int i = 0; i < 4; i++) {
        float4 o = make_float4(acc[i][0], acc[i][1], acc[i][2], acc[i][3]);
        *reinterpret_cast<float4*>(Y + (size_t)(t0 + ty * 4 + i) * C_DIM + h * DHD + tx * 4) = o;
    }
}

// ---------------- local windowed softmax attention (Y += ...) ----------------
// grid (T/64, H), 256 threads. Window = 128, q-tile = 64 (half window).
__global__ __launch_bounds__(256) void local_attn(
    const float* __restrict__ Q, const float* __restrict__ K,
    const float* __restrict__ V, float* __restrict__ Y)
{
    extern __shared__ float sm[];
    float (*Qs)[65]  = (float(*)[65])sm;                          // 64x65
    float (*Ks)[65]  = (float(*)[65])(sm + 64 * 65);              // 128x65
    float (*Vs)[65]  = (float(*)[65])(sm + 64 * 65 + 128 * 65);   // 128x65
    float (*Ss)[129] = (float(*)[129])(sm + 64 * 65 + 2 * 128 * 65); // 64x129

    int qt = blockIdx.x, h = blockIdx.y;
    int kvh = h >> 2;
    int tid = threadIdx.x, tx = tid & 15, ty = tid >> 4;
    int t0 = qt * 64;
    int w0 = (t0 / WINSZ) * WINSZ;
    int qoff = t0 - w0;            // 0 or 64
    int nk = qoff + 64;            // causal-reachable keys in window

    for (int f = tid; f < 64 * 16; f += 256) {
        int r = f >> 4, cv = (f & 15) * 4;
        float4 v = *reinterpret_cast<const float4*>(Q + (size_t)(t0 + r) * C_DIM + h * DHD + cv);
        Qs[r][cv + 0] = v.x; Qs[r][cv + 1] = v.y; Qs[r][cv + 2] = v.z; Qs[r][cv + 3] = v.w;
    }
    for (int f = tid; f < nk * 16; f += 256) {
        int r = f >> 4, cv = (f & 15) * 4;
        float4 kk4 = *reinterpret_cast<const float4*>(K + (size_t)(w0 + r) * (NKV * DHD) + kvh * DHD + cv);
        Ks[r][cv + 0] = kk4.x; Ks[r][cv + 1] = kk4.y; Ks[r][cv + 2] = kk4.z; Ks[r][cv + 3] = kk4.w;
        float4 vv4 = *reinterpret_cast<const float4*>(V + (size_t)(w0 + r) * (NKV * DHD) + kvh * DHD + cv);
        Vs[r][cv + 0] = vv4.x; Vs[r][cv + 1] = vv4.y; Vs[r][cv + 2] = vv4.z; Vs[r][cv + 3] = vv4.w;
    }
    __syncthreads();

    for (int half = 0; half < (nk >> 6); half++) {
        float sc[4][4] = {};
#pragma unroll
        for (int kk = 0; kk < 64; kk++) {
            float a[4], b[4];
#pragma unroll
            for (int i = 0; i < 4; i++) a[i] = Qs[ty * 4 + i][kk];
#pragma unroll
            for (int j = 0; j < 4; j++) b[j] = Ks[half * 64 + tx * 4 + j][kk];
#pragma unroll
            for (int i = 0; i < 4; i++)
#pragma unroll
                for (int j = 0; j < 4; j++) sc[i][j] += a[i] * b[j];
        }
#pragma unroll
        for (int i = 0; i < 4; i++) {
            int ti = qoff + ty * 4 + i;
#pragma unroll
            for (int j = 0; j < 4; j++) {
                int sj = half * 64 + tx * 4 + j;
                Ss[ty * 4 + i][sj] = (sj <= ti) ? sc[i][j] * 0.125f : neg_inf();
            }
        }
    }
    __syncthreads();

    // softmax: 4 lanes per row
    {
        int r = tid >> 2, g = tid & 3;
        float m = neg_inf();
        for (int c = g; c < nk; c += 4) m = fmaxf(m, Ss[r][c]);
        m = fmaxf(m, __shfl_xor_sync(0xffffffff, m, 1));
        m = fmaxf(m, __shfl_xor_sync(0xffffffff, m, 2));
        float sum = 0.f;
        for (int c = g; c < nk; c += 4) {
            float e = expf(Ss[r][c] - m);
            Ss[r][c] = e;
            sum += e;
        }
        sum += __shfl_xor_sync(0xffffffff, sum, 1);
        sum += __shfl_xor_sync(0xffffffff, sum, 2);
        float inv = 1.f / sum;
        for (int c = g; c < nk; c += 4) Ss[r][c] *= inv;
    }
    __syncthreads();

    float acc[4][4] = {};
    for (int kk = 0; kk < nk; kk++) {
        float p[4], vv[4];
#pragma unroll
        for (int i = 0; i < 4; i++) p[i] = Ss[ty * 4 + i][kk];
#pragma unroll
        for (int j = 0; j < 4; j++) vv[j] = Vs[kk][tx * 4 + j];
#pragma unroll
        for (int i = 0; i < 4; i++)
#pragma unroll
            for (int j = 0; j < 4; j++) acc[i][j] += p[i] * vv[j];
    }
#pragma unroll
    for (int i = 0; i < 4; i++) {
        float4* yp = reinterpret_cast<float4*>(Y + (size_t)(t0 + ty * 4 + i) * C_DIM + h * DHD + tx * 4);
        float4 o = *yp;
        o.x += acc[i][0]; o.y += acc[i][1]; o.z += acc[i][2]; o.w += acc[i][3];
        *yp = o;
    }
}

// ---------------- RMSNorm (in place), per row of C=1024 ----------------
__global__ __launch_bounds__(256) void rmsnorm_kernel(float* __restrict__ Y, const float* __restrict__ w)
{
    int t = blockIdx.x, tid = threadIdx.x;
    float4* yp = reinterpret_cast<float4*>(Y + (size_t)t * C_DIM + tid * 4);
    float4 v = *yp;
    float ss = v.x * v.x + v.y * v.y + v.z * v.z + v.w * v.w;
#pragma unroll
    for (int off = 16; off; off >>= 1) ss += __shfl_xor_sync(0xffffffff, ss, off);
    __shared__ float red[8];
    if ((tid & 31) == 0) red[tid >> 5] = ss;
    __syncthreads();
    if (tid < 8) {
        float s = red[tid];
        s += __shfl_xor_sync(0xff, s, 1);
        s += __shfl_xor_sync(0xff, s, 2);
        s += __shfl_xor_sync(0xff, s, 4);
        if (tid == 0) red[0] = s;
    }
    __syncthreads();
    float scale = rsqrtf(red[0] * (1.f / (float)C_DIM) + 1e-5f);
    float4 wv = *reinterpret_cast<const float4*>(w + tid * 4);
    v.x *= scale * wv.x; v.y *= scale * wv.y; v.z *= scale * wv.z; v.w *= scale * wv.w;
    *yp = v;
}

// ---------------- launch ----------------
extern "C" void kernel_launch(void* const* d_in, const int* in_sizes, int n_in,
                              void* d_out, int out_size)
{
    (void)in_sizes; (void)n_in; (void)out_size;
    const float* x    = (const float*)d_in[0];
    const float* Wq   = (const float*)d_in[1];
    const float* Wk   = (const float*)d_in[2];
    const float* Wv   = (const float*)d_in[3];
    const float* Wc   = (const float*)d_in[4];
    const float* Wg   = (const float*)d_in[5];
    const float* bg   = (const float*)d_in[6];
    const float* rmsw = (const float*)d_in[7];
    float* out = (float*)d_out;

    float *Q, *K, *V, *G, *D, *L, *Y;
    cudaGetSymbolAddress((void**)&Q, g_Q);
    cudaGetSymbolAddress((void**)&K, g_K);
    cudaGetSymbolAddress((void**)&V, g_V);
    cudaGetSymbolAddress((void**)&G, g_G);
    cudaGetSymbolAddress((void**)&D, g_D);
    cudaGetSymbolAddress((void**)&L, g_L);
    cudaGetSymbolAddress((void**)&Y, g_Y);

    // projections
    gemm64<<<dim3(C_DIM / 64, T_SEQ / 64), 256>>>(x, Wq, Q, T_SEQ, C_DIM, C_DIM);
    gemm64<<<dim3((NKV * DHD) / 64, T_SEQ / 64), 256>>>(x, Wk, K, T_SEQ, NKV * DHD, C_DIM);
    gemm64<<<dim3((NKV * DHD) / 64, T_SEQ / 64), 256>>>(x, Wv, V, T_SEQ, NKV * DHD, C_DIM);
    gate_kernel<<<T_SEQ, 256>>>(x, Wg, bg, G);
    scan_kernel<<<NH, 256>>>(G, D, L);

    // rotary
    rope_kernel<<<(T_SEQ * NH * 32 + 255) / 256, 256>>>(Q, NH);
    rope_kernel<<<(T_SEQ * NKV * 32 + 255) / 256, 256>>>(K, NKV);

    // attention
    size_t smemG = (size_t)(4 * 64 * 65 + 5 * 64) * sizeof(float);
    cudaFuncSetAttribute(global_attn, cudaFuncAttributeMaxDynamicSharedMemorySize, (int)smemG);
    global_attn<<<dim3(T_SEQ / 64, NH), 256, smemG>>>(Q, K, V, D, L, Y);

    size_t smemL = (size_t)(64 * 65 + 2 * 128 * 65 + 64 * 129) * sizeof(float);
    cudaFuncSetAttribute(local_attn, cudaFuncAttributeMaxDynamicSharedMemorySize, (int)smemL);
    local_attn<<<dim3(T_SEQ / 64, NH), 256, smemL>>>(Q, K, V, Y);

    // norm + output projection
    rmsnorm_kernel<<<T_SEQ, 256>>>(Y, rmsw);
    gemm64<<<dim3(C_DIM / 64, T_SEQ / 64), 256>>>(Y, Wc, out, T_SEQ, C_DIM, C_DIM);
}

// round 3
// speedup vs baseline: 1.7260x; 1.7260x over previous
#include <cuda_runtime.h>
#include <cuda_bf16.h>
#include <math.h>
#include <stdint.h>

#define T_SEQ 2048
#define C_DIM 1024
#define NH    16
#define NKV   4
#define DHD   64
#define WINSZ 128
#define PSTR  1536          /* fused projection row stride: Q(1024) | K(256) | V(256) */
#define KOFF  1024
#define VOFF  1280

// ---------------- scratch (no allocations allowed) ----------------
__device__ float g_P[T_SEQ * PSTR];          // fused Q|K|V projections
__device__ float g_G[NH * T_SEQ];
__device__ float g_D[NH * T_SEQ];
__device__ float g_L[NH * T_SEQ];
__device__ float g_Y[T_SEQ * C_DIM];
__device__ __nv_bfloat16 g_Wp_h[PSTR * C_DIM];   // transposed split proj weights [N][K]
__device__ __nv_bfloat16 g_Wp_l[PSTR * C_DIM];
__device__ __nv_bfloat16 g_Wc_h[C_DIM * C_DIM];
__device__ __nv_bfloat16 g_Wc_l[C_DIM * C_DIM];

__device__ __forceinline__ float neg_inf() { return __int_as_float(0xff800000); }
__device__ __forceinline__ float log_sigmoid_f(float x) {
    return fminf(x, 0.f) - log1pf(expf(-fabsf(x)));
}
__device__ __forceinline__ uint32_t cvta_smem(const void* p) {
    uint32_t a;
    asm("{ .reg .u64 t; cvta.to.shared.u64 t, %1; cvt.u32.u64 %0, t; }" : "=r"(a) : "l"(p));
    return a;
}
__device__ __forceinline__ uint32_t pack2bf(float a, float b) {
    __nv_bfloat162 t = __floats2bfloat162_rn(a, b);
    return *reinterpret_cast<uint32_t*>(&t);
}
__device__ __forceinline__ void ldsm4(uint32_t* r, uint32_t addr) {
    asm volatile("ldmatrix.sync.aligned.m8n8.x4.shared.b16 {%0,%1,%2,%3}, [%4];"
                 : "=r"(r[0]), "=r"(r[1]), "=r"(r[2]), "=r"(r[3]) : "r"(addr));
}
__device__ __forceinline__ void mma_bf16(float* c, const uint32_t* a, const uint32_t* b) {
    asm volatile(
        "mma.sync.aligned.m16n8k16.row.col.f32.bf16.bf16.f32 "
        "{%0,%1,%2,%3}, {%4,%5,%6,%7}, {%8,%9}, {%0,%1,%2,%3};"
        : "+f"(c[0]), "+f"(c[1]), "+f"(c[2]), "+f"(c[3])
        : "r"(a[0]), "r"(a[1]), "r"(a[2]), "r"(a[3]), "r"(b[0]), "r"(b[1]));
}
__device__ __forceinline__ void sts16(uint32_t addr, uint32_t a, uint32_t b, uint32_t c, uint32_t d) {
    asm volatile("st.shared.v4.b32 [%0], {%1,%2,%3,%4};" :: "r"(addr), "r"(a), "r"(b), "r"(c), "r"(d) : "memory");
}

// ---------------- weight transpose + bf16 split: W[K][N] -> Th/Tl[N][K] ----------------
__global__ __launch_bounds__(256) void transpose_split(
    const float* __restrict__ W, __nv_bfloat16* __restrict__ Th,
    __nv_bfloat16* __restrict__ Tl, int K, int N)
{
    __shared__ float s[32][33];
    int k0 = blockIdx.y * 32, n0 = blockIdx.x * 32;
    int tx = threadIdx.x & 31, ty = threadIdx.x >> 5;
#pragma unroll
    for (int i = 0; i < 4; i++) {
        int r = ty + i * 8;
        s[r][tx] = W[(size_t)(k0 + r) * N + n0 + tx];
    }
    __syncthreads();
#pragma unroll
    for (int i = 0; i < 4; i++) {
        int r = ty + i * 8;
        float v = s[tx][r];
        __nv_bfloat16 h = __float2bfloat16_rn(v);
        Th[(size_t)(n0 + r) * K + k0 + tx] = h;
        Tl[(size_t)(n0 + r) * K + k0 + tx] = __float2bfloat16_rn(v - __bfloat162float(h));
    }
}

// ---------------- bf16x3 tensor-core GEMM: C[M][N] = A[M][K](fp32) @ B[N][K]^T ----------------
// 128x128x32 CTA tile, 256 threads, 8 warps as 4(m) x 2(n), warp tile 32x64.
// smem rows: 128B (8 chunks of 16B), hi in chunks 0-3, lo in 4-7, phys chunk = logical ^ (row&7).
__global__ __launch_bounds__(256, 1) void gemm_mma(
    const float* __restrict__ A, const __nv_bfloat16* __restrict__ Bh,
    const __nv_bfloat16* __restrict__ Bl, float* __restrict__ C,
    int M, int N, int K)
{
    extern __shared__ char smc[];
    uint32_t sb = cvta_smem(smc);            // [stage 32KB][As 16KB | Bs 16KB]

    int tid = threadIdx.x, lane = tid & 31, warp = tid >> 5;
    int wm = warp & 3, wn = warp >> 2;
    int m0 = blockIdx.y * 128, n0 = blockIdx.x * 128;

    int row = tid & 127;
    bool isB = tid >= 128;
    const float* ag = A + (size_t)(m0 + row) * K;
    const __nv_bfloat16* bhg = Bh + (size_t)(n0 + row) * K;
    const __nv_bfloat16* blg = Bl + (size_t)(n0 + row) * K;

    float acc[2][8][4] = {};
    float4 pa[8];
    uint4 pbh[4], pbl[4];

    // prefetch kt = 0
    if (!isB) {
#pragma unroll
        for (int i = 0; i < 8; i++) pa[i] = *reinterpret_cast<const float4*>(ag + i * 4);
    } else {
#pragma unroll
        for (int c = 0; c < 4; c++) {
            pbh[c] = *reinterpret_cast<const uint4*>(bhg + c * 8);
            pbl[c] = *reinterpret_cast<const uint4*>(blg + c * 8);
        }
    }

    int nkt = K / 32;
    for (int kt = 0; kt < nkt; ++kt) {
        uint32_t stage = sb + (uint32_t)(kt & 1) * 32768u;
        uint32_t aB = stage, bB = stage + 16384u;

        // ---- stage current prefetch into smem ----
        if (!isB) {
            uint32_t dst = aB + (uint32_t)row * 128u;
            int rs = row & 7;
#pragma unroll
            for (int c = 0; c < 4; c++) {
                float4 v0 = pa[2 * c], v1 = pa[2 * c + 1];
                float h0 = __bfloat162float(__float2bfloat16_rn(v0.x));
                float h1 = __bfloat162float(__float2bfloat16_rn(v0.y));
                float h2 = __bfloat162float(__float2bfloat16_rn(v0.z));
                float h3 = __bfloat162float(__float2bfloat16_rn(v0.w));
                float h4 = __bfloat162float(__float2bfloat16_rn(v1.x));
                float h5 = __bfloat162float(__float2bfloat16_rn(v1.y));
                float h6 = __bfloat162float(__float2bfloat16_rn(v1.z));
                float h7 = __bfloat162float(__float2bfloat16_rn(v1.w));
                sts16(dst + (uint32_t)((c ^ rs) * 16),
                      pack2bf(h0, h1), pack2bf(h2, h3), pack2bf(h4, h5), pack2bf(h6, h7));
                sts16(dst + (uint32_t)(((4 + c) ^ rs) * 16),
                      pack2bf(v0.x - h0, v0.y - h1), pack2bf(v0.z - h2, v0.w - h3),
                      pack2bf(v1.x - h4, v1.y - h5), pack2bf(v1.z - h6, v1.w - h7));
            }
        } else {
            uint32_t dst = bB + (uint32_t)row * 128u;
            int rs = row & 7;
#pragma unroll
            for (int c = 0; c < 4; c++) {
                sts16(dst + (uint32_t)((c ^ rs) * 16), pbh[c].x, pbh[c].y, pbh[c].z, pbh[c].w);
                sts16(dst + (uint32_t)(((4 + c) ^ rs) * 16), pbl[c].x, pbl[c].y, pbl[c].z, pbl[c].w);
            }
        }
        __syncthreads();

        // ---- prefetch next k-tile ----
        if (kt + 1 < nkt) {
            int kb = (kt + 1) * 32;
            if (!isB) {
#pragma unroll
                for (int i = 0; i < 8; i++) pa[i] = *reinterpret_cast<const float4*>(ag + kb + i * 4);
            } else {
#pragma unroll
                for (int c = 0; c < 4; c++) {
                    pbh[c] = *reinterpret_cast<const uint4*>(bhg + kb + c * 8);
                    pbl[c] = *reinterpret_cast<const uint4*>(blg + kb + c * 8);
                }
            }
        }

        // ---- compute 2 k16 steps ----
#pragma unroll
        for (int s = 0; s < 2; s++) {
            uint32_t ahi[2][4], alo[2][4];
            int arow = wm * 32 + (lane & 15);
            int asel = lane >> 4;
#pragma unroll
            for (int t = 0; t < 2; t++) {
                int r = arow + t * 16;
                uint32_t base = aB + (uint32_t)r * 128u;
                ldsm4(ahi[t], base + (uint32_t)((((2 * s) + asel) ^ (r & 7)) * 16));
                ldsm4(alo[t], base + (uint32_t)(((4 + 2 * s + asel) ^ (r & 7)) * 16));
            }
            uint32_t bhi[4][4], blo[4][4];
            int nrow = wn * 64 + (lane & 7) + ((lane >> 4) << 3);
            int bsel = (lane >> 3) & 1;
#pragma unroll
            for (int g = 0; g < 4; g++) {
                int r = nrow + g * 16;
                uint32_t base = bB + (uint32_t)r * 128u;
                ldsm4(bhi[g], base + (uint32_t)((((2 * s) + bsel) ^ (r & 7)) * 16));
                ldsm4(blo[g], base + (uint32_t)(((4 + 2 * s + bsel) ^ (r & 7)) * 16));
            }
#pragma unroll
            for (int t = 0; t < 2; t++)
#pragma unroll
                for (int j = 0; j < 8; j++) {
                    const uint32_t* bh2 = &bhi[j >> 1][2 * (j & 1)];
                    const uint32_t* bl2 = &blo[j >> 1][2 * (j & 1)];
                    mma_bf16(acc[t][j], ahi[t], bh2);
                    mma_bf16(acc[t][j], ahi[t], bl2);
                    mma_bf16(acc[t][j], alo[t], bh2);
                }
        }
    }

    // ---- epilogue ----
#pragma unroll
    for (int t = 0; t < 2; t++) {
        int r0 = m0 + wm * 32 + t * 16 + (lane >> 2);
#pragma unroll
        for (int j = 0; j < 8; j++) {
            int col = n0 + wn * 64 + j * 8 + 2 * (lane & 3);
            *reinterpret_cast<float2*>(C + (size_t)r0 * N + col) = make_float2(acc[t][j][0], acc[t][j][1]);
            *reinterpret_cast<float2*>(C + (size_t)(r0 + 8) * N + col) = make_float2(acc[t][j][2], acc[t][j][3]);
        }
    }
}

// ---------------- gate logits ----------------
__global__ __launch_bounds__(256) void gate_kernel(
    const float* __restrict__ x, const float* __restrict__ Wg,
    const float* __restrict__ bg, float* __restrict__ G)
{
    __shared__ float xs[C_DIM];
    __shared__ float red[16][17];
    int t = blockIdx.x, tid = threadIdx.x;
    float4 v = *reinterpret_cast<const float4*>(x + (size_t)t * C_DIM + tid * 4);
    xs[tid * 4 + 0] = v.x; xs[tid * 4 + 1] = v.y;
    xs[tid * 4 + 2] = v.z; xs[tid * 4 + 3] = v.w;
    __syncthreads();
    int h = tid & 15, part = tid >> 4;
    float s = 0.f;
#pragma unroll 8
    for (int i = 0; i < 64; i++) {
        int c = part * 64 + i;
        s += xs[c] * Wg[c * NH + h];
    }
    red[part][h] = s;
    __syncthreads();
    if (tid < 16) {
        float acc = bg[tid];
#pragma unroll
        for (int p = 0; p < 16; p++) acc += red[p][tid];
        G[tid * T_SEQ + t] = acc;
    }
}

// ---------------- per-head scan ----------------
__global__ __launch_bounds__(256) void scan_kernel(
    const float* __restrict__ G, float* __restrict__ D, float* __restrict__ L)
{
    int h = blockIdx.x, tid = threadIdx.x;
    const float* g = G + h * T_SEQ;
    float vals[8];
    float run = 0.f;
#pragma unroll
    for (int i = 0; i < 8; i++) {
        float gg = g[tid * 8 + i];
        run += log_sigmoid_f(gg);
        vals[i] = run;
        L[h * T_SEQ + tid * 8 + i] = log_sigmoid_f(-gg);
    }
    __shared__ float s[256];
    s[tid] = run;
    __syncthreads();
    for (int off = 1; off < 256; off <<= 1) {
        float v = 0.f;
        if (tid >= off) v = s[tid - off];
        __syncthreads();
        s[tid] += v;
        __syncthreads();
    }
    float excl = s[tid] - run;
#pragma unroll
    for (int i = 0; i < 8; i++) D[h * T_SEQ + tid * 8 + i] = vals[i] + excl;
}

// ---------------- RoPE ----------------
__global__ __launch_bounds__(256) void rope_kernel(float* __restrict__ P, int heads, int stride, int colOff)
{
    int idx = blockIdx.x * blockDim.x + threadIdx.x;
    int total = T_SEQ * heads * 32;
    if (idx >= total) return;
    int d = idx & 31;
    int h = (idx >> 5) % heads;
    int t = idx / (heads * 32);
    float inv = expf(-(float)(2 * d) * (9.210340371976184f / 64.f));
    float theta = (float)t * inv;
    float sn, cs;
    sincosf(theta, &sn, &cs);
    float* p = P + (size_t)t * stride + colOff + h * DHD;
    float a = p[d], b = p[d + 32];
    p[d]      = a * cs - b * sn;
    p[d + 32] = b * cs + a * sn;
}

// ---------------- global gated-decay attention ----------------
__global__ __launch_bounds__(256) void global_attn(
    const float* __restrict__ P, const float* __restrict__ D,
    const float* __restrict__ L, float* __restrict__ Y)
{
    extern __shared__ float sm[];
    float (*Qs)[65] = (float(*)[65])sm;
    float (*Ks)[65] = (float(*)[65])(sm + 64 * 65);
    float (*Vs)[65] = (float(*)[65])(sm + 2 * 64 * 65);
    float (*Ss)[65] = (float(*)[65])(sm + 3 * 64 * 65);
    float* Dq   = sm + 4 * 64 * 65;
    float* rowE = Dq + 64;
    float* Ds   = rowE + 64;
    float* Ls   = Ds + 64;
    float* colE = Ls + 64;

    int qt = blockIdx.x, h = blockIdx.y;
    int kvh = h >> 2;
    int tid = threadIdx.x, tx = tid & 15, ty = tid >> 4;
    int t0 = qt * 64;

    for (int f = tid; f < 64 * 16; f += 256) {
        int r = f >> 4, cv = (f & 15) * 4;
        float4 v = *reinterpret_cast<const float4*>(P + (size_t)(t0 + r) * PSTR + h * DHD + cv);
        Qs[r][cv + 0] = v.x; Qs[r][cv + 1] = v.y; Qs[r][cv + 2] = v.z; Qs[r][cv + 3] = v.w;
    }
    if (tid < 64) Dq[tid] = D[h * T_SEQ + t0 + tid];
    __syncthreads();
    float dq0 = Dq[0];
    if (tid < 64) rowE[tid] = expf(Dq[tid] - dq0);

    float acc[4][4] = {};
    for (int st = qt; st >= 0; st--) {
        int s0 = st * 64;
        if (st < qt) {
            float dend = D[h * T_SEQ + s0 + 63];
            if (dq0 - dend < -88.f) break;
        }
        __syncthreads();
        for (int f = tid; f < 64 * 16; f += 256) {
            int r = f >> 4, cv = (f & 15) * 4;
            float4 kk4 = *reinterpret_cast<const float4*>(P + (size_t)(s0 + r) * PSTR + KOFF + kvh * DHD + cv);
            Ks[r][cv + 0] = kk4.x; Ks[r][cv + 1] = kk4.y; Ks[r][cv + 2] = kk4.z; Ks[r][cv + 3] = kk4.w;
            float4 vv4 = *reinterpret_cast<const float4*>(P + (size_t)(s0 + r) * PSTR + VOFF + kvh * DHD + cv);
            Vs[r][cv + 0] = vv4.x; Vs[r][cv + 1] = vv4.y; Vs[r][cv + 2] = vv4.z; Vs[r][cv + 3] = vv4.w;
        }
        if (tid < 64) {
            float ds = D[h * T_SEQ + s0 + tid];
            float ls = L[h * T_SEQ + s0 + tid];
            Ds[tid] = ds; Ls[tid] = ls;
            colE[tid] = expf(dq0 - ds + ls);
        }
        __syncthreads();

        float sc[4][4] = {};
#pragma unroll
        for (int kk = 0; kk < 64; kk++) {
            float a[4], b[4];
#pragma unroll
            for (int i = 0; i < 4; i++) a[i] = Qs[ty * 4 + i][kk];
#pragma unroll
            for (int j = 0; j < 4; j++) b[j] = Ks[tx * 4 + j][kk];
#pragma unroll
            for (int i = 0; i < 4; i++)
#pragma unroll
                for (int j = 0; j < 4; j++) sc[i][j] += a[i] * b[j];
        }
        if (st == qt) {
#pragma unroll
            for (int i = 0; i < 4; i++) {
                int ti = ty * 4 + i;
#pragma unroll
                for (int j = 0; j < 4; j++) {
                    int sj = tx * 4 + j;
                    float w = (sj <= ti) ? expf(Dq[ti] - Ds[sj] + Ls[sj]) : 0.f;
                    Ss[ti][sj] = sc[i][j] * w;
                }
            }
        } else {
#pragma unroll
            for (int i = 0; i < 4; i++) {
                float re = rowE[ty * 4 + i];
#pragma unroll
                for (int j = 0; j < 4; j++)
                    Ss[ty * 4 + i][tx * 4 + j] = sc[i][j] * (re * colE[tx * 4 + j]);
            }
        }
        __syncthreads();
#pragma unroll
        for (int kk = 0; kk < 64; kk++) {
            float p[4], vv[4];
#pragma unroll
            for (int i = 0; i < 4; i++) p[i] = Ss[ty * 4 + i][kk];
#pragma unroll
            for (int j = 0; j < 4; j++) vv[j] = Vs[kk][tx * 4 + j];
#pragma unroll
            for (int i = 0; i < 4; i++)
#pragma unroll
                for (int j = 0; j < 4; j++) acc[i][j] += p[i] * vv[j];
        }
    }
#pragma unroll
    for (int i = 0; i < 4; i++) {
        float4 o = make_float4(acc[i][0], acc[i][1], acc[i][2], acc[i][3]);
        *reinterpret_cast<float4*>(Y + (size_t)(t0 + ty * 4 + i) * C_DIM + h * DHD + tx * 4) = o;
    }
}

// ---------------- local windowed attention ----------------
__global__ __launch_bounds__(256) void local_attn(
    const float* __restrict__ P, float* __restrict__ Y)
{
    extern __shared__ float sm[];
    float (*Qs)[65]  = (float(*)[65])sm;
    float (*Ks)[65]  = (float(*)[65])(sm + 64 * 65);
    float (*Vs)[65]  = (float(*)[65])(sm + 64 * 65 + 128 * 65);
    float (*Ss)[129] = (float(*)[129])(sm + 64 * 65 + 2 * 128 * 65);

    int qt = blockIdx.x, h = blockIdx.y;
    int kvh = h >> 2;
    int tid = threadIdx.x, tx = tid & 15, ty = tid >> 4;
    int t0 = qt * 64;
    int w0 = (t0 / WINSZ) * WINSZ;
    int qoff = t0 - w0;
    int nk = qoff + 64;

    for (int f = tid; f < 64 * 16; f += 256) {
        int r = f >> 4, cv = (f & 15) * 4;
        float4 v = *reinterpret_cast<const float4*>(P + (size_t)(t0 + r) * PSTR + h * DHD + cv);
        Qs[r][cv + 0] = v.x; Qs[r][cv + 1] = v.y; Qs[r][cv + 2] = v.z; Qs[r][cv + 3] = v.w;
    }
    for (int f = tid; f < nk * 16; f += 256) {
        int r = f >> 4, cv = (f & 15) * 4;
        float4 kk4 = *reinterpret_cast<const float4*>(P + (size_t)(w0 + r) * PSTR + KOFF + kvh * DHD + cv);
        Ks[r][cv + 0] = kk4.x; Ks[r][cv + 1] = kk4.y; Ks[r][cv + 2] = kk4.z; Ks[r][cv + 3] = kk4.w;
        float4 vv4 = *reinterpret_cast<const float4*>(P + (size_t)(w0 + r) * PSTR + VOFF + kvh * DHD + cv);
        Vs[r][cv + 0] = vv4.x; Vs[r][cv + 1] = vv4.y; Vs[r][cv + 2] = vv4.z; Vs[r][cv + 3] = vv4.w;
    }
    __syncthreads();

    for (int half = 0; half < (nk >> 6); half++) {
        float sc[4][4] = {};
#pragma unroll
        for (int kk = 0; kk < 64; kk++) {
            float a[4], b[4];
#pragma unroll
            for (int i = 0; i < 4; i++) a[i] = Qs[ty * 4 + i][kk];
#pragma unroll
            for (int j = 0; j < 4; j++) b[j] = Ks[half * 64 + tx * 4 + j][kk];
#pragma unroll
            for (int i = 0; i < 4; i++)
#pragma unroll
                for (int j = 0; j < 4; j++) sc[i][j] += a[i] * b[j];
        }
#pragma unroll
        for (int i = 0; i < 4; i++) {
            int ti = qoff + ty * 4 + i;
#pragma unroll
            for (int j = 0; j < 4; j++) {
                int sj = half * 64 + tx * 4 + j;
                Ss[ty * 4 + i][sj] = (sj <= ti) ? sc[i][j] * 0.125f : neg_inf();
            }
        }
    }
    __syncthreads();

    {
        int r = tid >> 2, g = tid & 3;
        float m = neg_inf();
        for (int c = g; c < nk; c += 4) m = fmaxf(m, Ss[r][c]);
        m = fmaxf(m, __shfl_xor_sync(0xffffffff, m, 1));
        m = fmaxf(m, __shfl_xor_sync(0xffffffff, m, 2));
        float sum = 0.f;
        for (int c = g; c < nk; c += 4) {
            float e = expf(Ss[r][c] - m);
            Ss[r][c] = e;
            sum += e;
        }
        sum += __shfl_xor_sync(0xffffffff, sum, 1);
        sum += __shfl_xor_sync(0xffffffff, sum, 2);
        float inv = 1.f / sum;
        for (int c = g; c < nk; c += 4) Ss[r][c] *= inv;
    }
    __syncthreads();

    float acc[4][4] = {};
    for (int kk = 0; kk < nk; kk++) {
        float p[4], vv[4];
#pragma unroll
        for (int i = 0; i < 4; i++) p[i] = Ss[ty * 4 + i][kk];
#pragma unroll
        for (int j = 0; j < 4; j++) vv[j] = Vs[kk][tx * 4 + j];
#pragma unroll
        for (int i = 0; i < 4; i++)
#pragma unroll
            for (int j = 0; j < 4; j++) acc[i][j] += p[i] * vv[j];
    }
#pragma unroll
    for (int i = 0; i < 4; i++) {
        float4* yp = reinterpret_cast<float4*>(Y + (size_t)(t0 + ty * 4 + i) * C_DIM + h * DHD + tx * 4);
        float4 o = *yp;
        o.x += acc[i][0]; o.y += acc[i][1]; o.z += acc[i][2]; o.w += acc[i][3];
        *yp = o;
    }
}

// ---------------- RMSNorm ----------------
__global__ __launch_bounds__(256) void rmsnorm_kernel(float* __restrict__ Y, const float* __restrict__ w)
{
    int t = blockIdx.x, tid = threadIdx.x;
    float4* yp = reinterpret_cast<float4*>(Y + (size_t)t * C_DIM + tid * 4);
    float4 v = *yp;
    float ss = v.x * v.x + v.y * v.y + v.z * v.z + v.w * v.w;
#pragma unroll
    for (int off = 16; off; off >>= 1) ss += __shfl_xor_sync(0xffffffff, ss, off);
    __shared__ float red[8];
    if ((tid & 31) == 0) red[tid >> 5] = ss;
    __syncthreads();
    if (tid < 8) {
        float s = red[tid];
        s += __shfl_xor_sync(0xff, s, 1);
        s += __shfl_xor_sync(0xff, s, 2);
        s += __shfl_xor_sync(0xff, s, 4);
        if (tid == 0) red[0] = s;
    }
    __syncthreads();
    float scale = rsqrtf(red[0] * (1.f / (float)C_DIM) + 1e-5f);
    float4 wv = *reinterpret_cast<const float4*>(w + tid * 4);
    v.x *= scale * wv.x; v.y *= scale * wv.y; v.z *= scale * wv.z; v.w *= scale * wv.w;
    *yp = v;
}

// ---------------- launch ----------------
extern "C" void kernel_launch(void* const* d_in, const int* in_sizes, int n_in,
                              void* d_out, int out_size)
{
    (void)in_sizes; (void)n_in; (void)out_size;
    const float* x    = (const float*)d_in[0];
    const float* Wq   = (const float*)d_in[1];
    const float* Wk   = (const float*)d_in[2];
    const float* Wv   = (const float*)d_in[3];
    const float* Wc   = (const float*)d_in[4];
    const float* Wg   = (const float*)d_in[5];
    const float* bg   = (const float*)d_in[6];
    const float* rmsw = (const float*)d_in[7];
    float* out = (float*)d_out;

    float *P, *G, *D, *L, *Y;
    __nv_bfloat16 *Wph, *Wpl, *Wch, *Wcl;
    cudaGetSymbolAddress((void**)&P, g_P);
    cudaGetSymbolAddress((void**)&G, g_G);
    cudaGetSymbolAddress((void**)&D, g_D);
    cudaGetSymbolAddress((void**)&L, g_L);
    cudaGetSymbolAddress((void**)&Y, g_Y);
    cudaGetSymbolAddress((void**)&Wph, g_Wp_h);
    cudaGetSymbolAddress((void**)&Wpl, g_Wp_l);
    cudaGetSymbolAddress((void**)&Wch, g_Wc_h);
    cudaGetSymbolAddress((void**)&Wcl, g_Wc_l);

    const int KD = C_DIM;

    // weight transpose + bf16 split (fused projection weight rows: Q | K | V)
    transpose_split<<<dim3(C_DIM / 32, KD / 32), 256>>>(Wq, Wph, Wpl, KD, C_DIM);
    transpose_split<<<dim3(256 / 32, KD / 32), 256>>>(Wk, Wph + (size_t)KOFF * KD, Wpl + (size_t)KOFF * KD, KD, 256);
    transpose_split<<<dim3(256 / 32, KD / 32), 256>>>(Wv, Wph + (size_t)VOFF * KD, Wpl + (size_t)VOFF * KD, KD, 256);
    transpose_split<<<dim3(C_DIM / 32, KD / 32), 256>>>(Wc, Wch, Wcl, KD, C_DIM);

    // fused Q|K|V projection on tensor cores (bf16x3)
    size_t smemTC = 65536;
    cudaFuncSetAttribute(gemm_mma, cudaFuncAttributeMaxDynamicSharedMemorySize, (int)smemTC);
    gemm_mma<<<dim3(PSTR / 128, T_SEQ / 128), 256, smemTC>>>(x, Wph, Wpl, P, T_SEQ, PSTR, KD);

    gate_kernel<<<T_SEQ, 256>>>(x, Wg, bg, G);
    scan_kernel<<<NH, 256>>>(G, D, L);

    rope_kernel<<<(T_SEQ * NH * 32 + 255) / 256, 256>>>(P, NH, PSTR, 0);
    rope_kernel<<<(T_SEQ * NKV * 32 + 255) / 256, 256>>>(P, NKV, PSTR, KOFF);

    size_t smemG = (size_t)(4 * 64 * 65 + 5 * 64) * sizeof(float);
    cudaFuncSetAttribute(global_attn, cudaFuncAttributeMaxDynamicSharedMemorySize, (int)smemG);
    global_attn<<<dim3(T_SEQ / 64, NH), 256, smemG>>>(P, D, L, Y);

    size_t smemL = (size_t)(64 * 65 + 2 * 128 * 65 + 64 * 129) * sizeof(float);
    cudaFuncSetAttribute(local_attn, cudaFuncAttributeMaxDynamicSharedMemorySize, (int)smemL);
    local_attn<<<dim3(T_SEQ / 64, NH), 256, smemL>>>(P, Y);

    rmsnorm_kernel<<<T_SEQ, 256>>>(Y, rmsw);
    gemm_mma<<<dim3(C_DIM / 128, T_SEQ / 128), 256, smemTC>>>(Y, Wch, Wcl, out, T_SEQ, C_DIM, KD);
}

// round 4
// speedup vs baseline: 2.2946x; 1.3295x over previous
#include <cuda_runtime.h>
#include <cuda_bf16.h>
#include <math.h>
#include <stdint.h>

#define T_SEQ 2048
#define C_DIM 1024
#define NH    16
#define NKV   4
#define DHD   64
#define WINSZ 128
#define PSTR  1536          /* fused projection row stride: Q(1024) | K(256) | V(256) */
#define KOFF  1024
#define VOFF  1280

// ---------------- scratch (no allocations allowed) ----------------
__device__ float g_P[T_SEQ * PSTR];          // fused Q|K|V projections
__device__ float g_G[NH * T_SEQ];
__device__ float g_D[NH * T_SEQ];
__device__ float g_L[NH * T_SEQ];
__device__ float g_Y[T_SEQ * C_DIM];
__device__ __nv_bfloat16 g_Wp_h[PSTR * C_DIM];   // transposed split proj weights [N][K]
__device__ __nv_bfloat16 g_Wp_l[PSTR * C_DIM];
__device__ __nv_bfloat16 g_Wc_h[C_DIM * C_DIM];
__device__ __nv_bfloat16 g_Wc_l[C_DIM * C_DIM];

__device__ __forceinline__ float neg_inf() { return __int_as_float(0xff800000); }
__device__ __forceinline__ float log_sigmoid_f(float x) {
    return fminf(x, 0.f) - log1pf(expf(-fabsf(x)));
}
__device__ __forceinline__ uint32_t cvta_smem(const void* p) {
    uint32_t a;
    asm("{ .reg .u64 t; cvta.to.shared.u64 t, %1; cvt.u32.u64 %0, t; }" : "=r"(a) : "l"(p));
    return a;
}
__device__ __forceinline__ uint32_t pack2bf(float a, float b) {
    __nv_bfloat162 t = __floats2bfloat162_rn(a, b);
    return *reinterpret_cast<uint32_t*>(&t);
}
__device__ __forceinline__ void ldsm4(uint32_t* r, uint32_t addr) {
    asm volatile("ldmatrix.sync.aligned.m8n8.x4.shared.b16 {%0,%1,%2,%3}, [%4];"
                 : "=r"(r[0]), "=r"(r[1]), "=r"(r[2]), "=r"(r[3]) : "r"(addr));
}
__device__ __forceinline__ void ldsm4t(uint32_t* r, uint32_t addr) {
    asm volatile("ldmatrix.sync.aligned.m8n8.x4.trans.shared.b16 {%0,%1,%2,%3}, [%4];"
                 : "=r"(r[0]), "=r"(r[1]), "=r"(r[2]), "=r"(r[3]) : "r"(addr));
}
__device__ __forceinline__ void mma_bf16(float* c, const uint32_t* a, const uint32_t* b) {
    asm volatile(
        "mma.sync.aligned.m16n8k16.row.col.f32.bf16.bf16.f32 "
        "{%0,%1,%2,%3}, {%4,%5,%6,%7}, {%8,%9}, {%0,%1,%2,%3};"
        : "+f"(c[0]), "+f"(c[1]), "+f"(c[2]), "+f"(c[3])
        : "r"(a[0]), "r"(a[1]), "r"(a[2]), "r"(a[3]), "r"(b[0]), "r"(b[1]));
}
__device__ __forceinline__ void sts16(uint32_t addr, uint32_t a, uint32_t b, uint32_t c, uint32_t d) {
    asm volatile("st.shared.v4.b32 [%0], {%1,%2,%3,%4};" :: "r"(addr), "r"(a), "r"(b), "r"(c), "r"(d) : "memory");
}
__device__ __forceinline__ void sts8(uint32_t addr, uint32_t a, uint32_t b) {
    asm volatile("st.shared.v2.b32 [%0], {%1,%2};" :: "r"(addr), "r"(a), "r"(b) : "memory");
}
__device__ __forceinline__ void sts4(uint32_t addr, uint32_t a) {
    asm volatile("st.shared.b32 [%0], %1;" :: "r"(addr), "r"(a) : "memory");
}

// load 64x64 fp32 tile -> split bf16 hi/lo into swizzled smem (128B rows)
__device__ __forceinline__ void load_split_tile(
    const float* __restrict__ gsrc, uint32_t smH, uint32_t smL, int tid)
{
#pragma unroll
    for (int i = 0; i < 4; i++) {
        int f = tid + i * 256;
        int r = f >> 4, q4 = f & 15;
        float4 v = *reinterpret_cast<const float4*>(gsrc + (size_t)r * PSTR + q4 * 4);
        float hx = __bfloat162float(__float2bfloat16_rn(v.x));
        float hy = __bfloat162float(__float2bfloat16_rn(v.y));
        float hz = __bfloat162float(__float2bfloat16_rn(v.z));
        float hw = __bfloat162float(__float2bfloat16_rn(v.w));
        uint32_t phys = (uint32_t)r * 128u + (uint32_t)(((q4 >> 1) ^ (r & 7)) * 16) + (uint32_t)((q4 & 1) * 8);
        sts8(smH + phys, pack2bf(hx, hy), pack2bf(hz, hw));
        sts8(smL + phys, pack2bf(v.x - hx, v.y - hy), pack2bf(v.z - hz, v.w - hw));
    }
}

// ---------------- weight transpose + bf16 split: W[K][N] -> Th/Tl[N][K] ----------------
__global__ __launch_bounds__(256) void transpose_split(
    const float* __restrict__ W, __nv_bfloat16* __restrict__ Th,
    __nv_bfloat16* __restrict__ Tl, int K, int N)
{
    __shared__ float s[32][33];
    int k0 = blockIdx.y * 32, n0 = blockIdx.x * 32;
    int tx = threadIdx.x & 31, ty = threadIdx.x >> 5;
#pragma unroll
    for (int i = 0; i < 4; i++) {
        int r = ty + i * 8;
        s[r][tx] = W[(size_t)(k0 + r) * N + n0 + tx];
    }
    __syncthreads();
#pragma unroll
    for (int i = 0; i < 4; i++) {
        int r = ty + i * 8;
        float v = s[tx][r];
        __nv_bfloat16 h = __float2bfloat16_rn(v);
        Th[(size_t)(n0 + r) * K + k0 + tx] = h;
        Tl[(size_t)(n0 + r) * K + k0 + tx] = __float2bfloat16_rn(v - __bfloat162float(h));
    }
}

// ---------------- bf16x3 tensor-core GEMM ----------------
__global__ __launch_bounds__(256, 1) void gemm_mma(
    const float* __restrict__ A, const __nv_bfloat16* __restrict__ Bh,
    const __nv_bfloat16* __restrict__ Bl, float* __restrict__ C,
    int M, int N, int K)
{
    extern __shared__ char smc[];
    uint32_t sb = cvta_smem(smc);

    int tid = threadIdx.x, lane = tid & 31, warp = tid >> 5;
    int wm = warp & 3, wn = warp >> 2;
    int m0 = blockIdx.y * 128, n0 = blockIdx.x * 128;

    int row = tid & 127;
    bool isB = tid >= 128;
    const float* ag = A + (size_t)(m0 + row) * K;
    const __nv_bfloat16* bhg = Bh + (size_t)(n0 + row) * K;
    const __nv_bfloat16* blg = Bl + (size_t)(n0 + row) * K;

    float acc[2][8][4] = {};
    float4 pa[8];
    uint4 pbh[4], pbl[4];

    if (!isB) {
#pragma unroll
        for (int i = 0; i < 8; i++) pa[i] = *reinterpret_cast<const float4*>(ag + i * 4);
    } else {
#pragma unroll
        for (int c = 0; c < 4; c++) {
            pbh[c] = *reinterpret_cast<const uint4*>(bhg + c * 8);
            pbl[c] = *reinterpret_cast<const uint4*>(blg + c * 8);
        }
    }

    int nkt = K / 32;
    for (int kt = 0; kt < nkt; ++kt) {
        uint32_t stage = sb + (uint32_t)(kt & 1) * 32768u;
        uint32_t aB = stage, bB = stage + 16384u;

        if (!isB) {
            uint32_t dst = aB + (uint32_t)row * 128u;
            int rs = row & 7;
#pragma unroll
            for (int c = 0; c < 4; c++) {
                float4 v0 = pa[2 * c], v1 = pa[2 * c + 1];
                float h0 = __bfloat162float(__float2bfloat16_rn(v0.x));
                float h1 = __bfloat162float(__float2bfloat16_rn(v0.y));
                float h2 = __bfloat162float(__float2bfloat16_rn(v0.z));
                float h3 = __bfloat162float(__float2bfloat16_rn(v0.w));
                float h4 = __bfloat162float(__float2bfloat16_rn(v1.x));
                float h5 = __bfloat162float(__float2bfloat16_rn(v1.y));
                float h6 = __bfloat162float(__float2bfloat16_rn(v1.z));
                float h7 = __bfloat162float(__float2bfloat16_rn(v1.w));
                sts16(dst + (uint32_t)((c ^ rs) * 16),
                      pack2bf(h0, h1), pack2bf(h2, h3), pack2bf(h4, h5), pack2bf(h6, h7));
                sts16(dst + (uint32_t)(((4 + c) ^ rs) * 16),
                      pack2bf(v0.x - h0, v0.y - h1), pack2bf(v0.z - h2, v0.w - h3),
                      pack2bf(v1.x - h4, v1.y - h5), pack2bf(v1.z - h6, v1.w - h7));
            }
        } else {
            uint32_t dst = bB + (uint32_t)row * 128u;
            int rs = row & 7;
#pragma unroll
            for (int c = 0; c < 4; c++) {
                sts16(dst + (uint32_t)((c ^ rs) * 16), pbh[c].x, pbh[c].y, pbh[c].z, pbh[c].w);
                sts16(dst + (uint32_t)(((4 + c) ^ rs) * 16), pbl[c].x, pbl[c].y, pbl[c].z, pbl[c].w);
            }
        }
        __syncthreads();

        if (kt + 1 < nkt) {
            int kb = (kt + 1) * 32;
            if (!isB) {
#pragma unroll
                for (int i = 0; i < 8; i++) pa[i] = *reinterpret_cast<const float4*>(ag + kb + i * 4);
            } else {
#pragma unroll
                for (int c = 0; c < 4; c++) {
                    pbh[c] = *reinterpret_cast<const uint4*>(bhg + kb + c * 8);
                    pbl[c] = *reinterpret_cast<const uint4*>(blg + kb + c * 8);
                }
            }
        }

#pragma unroll
        for (int s = 0; s < 2; s++) {
            uint32_t ahi[2][4], alo[2][4];
            int arow = wm * 32 + (lane & 15);
            int asel = lane >> 4;
#pragma unroll
            for (int t = 0; t < 2; t++) {
                int r = arow + t * 16;
                uint32_t base = aB + (uint32_t)r * 128u;
                ldsm4(ahi[t], base + (uint32_t)((((2 * s) + asel) ^ (r & 7)) * 16));
                ldsm4(alo[t], base + (uint32_t)(((4 + 2 * s + asel) ^ (r & 7)) * 16));
            }
            uint32_t bhi[4][4], blo[4][4];
            int nrow = wn * 64 + (lane & 7) + ((lane >> 4) << 3);
            int bsel = (lane >> 3) & 1;
#pragma unroll
            for (int g = 0; g < 4; g++) {
                int r = nrow + g * 16;
                uint32_t base = bB + (uint32_t)r * 128u;
                ldsm4(bhi[g], base + (uint32_t)((((2 * s) + bsel) ^ (r & 7)) * 16));
                ldsm4(blo[g], base + (uint32_t)(((4 + 2 * s + bsel) ^ (r & 7)) * 16));
            }
#pragma unroll
            for (int t = 0; t < 2; t++)
#pragma unroll
                for (int j = 0; j < 8; j++) {
                    const uint32_t* bh2 = &bhi[j >> 1][2 * (j & 1)];
                    const uint32_t* bl2 = &blo[j >> 1][2 * (j & 1)];
                    mma_bf16(acc[t][j], ahi[t], bh2);
                    mma_bf16(acc[t][j], ahi[t], bl2);
                    mma_bf16(acc[t][j], alo[t], bh2);
                }
        }
    }

#pragma unroll
    for (int t = 0; t < 2; t++) {
        int r0 = m0 + wm * 32 + t * 16 + (lane >> 2);
#pragma unroll
        for (int j = 0; j < 8; j++) {
            int col = n0 + wn * 64 + j * 8 + 2 * (lane & 3);
            *reinterpret_cast<float2*>(C + (size_t)r0 * N + col) = make_float2(acc[t][j][0], acc[t][j][1]);
            *reinterpret_cast<float2*>(C + (size_t)(r0 + 8) * N + col) = make_float2(acc[t][j][2], acc[t][j][3]);
        }
    }
}

// ---------------- fused global-decay + local-window attention (tensor cores) ----------------
// grid (T/64, H), 256 threads = 8 warps (wm 0..3 x wn 0..1). Writes Y = y_global + y_local.
// smem: Qh/Ql 16K | Kh/Kl 16K (Ph/Pl alias) | Vh/Vl 16K | Ss 64x132 fp32 | scalars
#define OFF_Q  0u
#define OFF_K  16384u
#define OFF_V  32768u
#define OFF_S  49152u
#define SSTR   132
#define OFF_SC (49152u + 64u * SSTR * 4u)

__global__ __launch_bounds__(256) void attn_fused(
    const float* __restrict__ P, const float* __restrict__ D,
    const float* __restrict__ L, float* __restrict__ Y)
{
    extern __shared__ char smc[];
    uint32_t sb = cvta_smem(smc);
    float* smS  = reinterpret_cast<float*>(smc + OFF_S);
    float* Dq   = reinterpret_cast<float*>(smc + OFF_SC);
    float* rowE = Dq + 64;
    float* Ds   = rowE + 64;
    float* Ls   = Ds + 64;
    float* colE = Ls + 64;

    int qt = blockIdx.x, h = blockIdx.y;
    int kvh = h >> 2;
    int tid = threadIdx.x, lane = tid & 31, warp = tid >> 5;
    int wm = warp & 3, wn = warp >> 2;
    int t0 = qt * 64;
    int w0 = (t0 / WINSZ) * WINSZ;
    int wt0 = w0 / 64;
    int nk = t0 - w0 + 64;           // 64 or 128 window keys

    // Q tile (with split), decay row data
    load_split_tile(P + (size_t)t0 * PSTR + h * DHD, sb + OFF_Q, sb + OFF_Q + 8192u, tid);
    if (tid < 64) Dq[tid] = D[h * T_SEQ + t0 + tid];
    __syncthreads();
    float dq0 = Dq[0];
    if (tid < 64) rowE[tid] = expf(Dq[tid] - dq0);

    // fragment row/col indices for this thread
    int fr0 = wm * 16 + (lane >> 2);          // rows fr0, fr0+8
    int fcb = wn * 32 + 2 * (lane & 3);       // col base; cols fcb+8j, fcb+8j+1

    float oacc[4][4] = {};                     // PV accumulator (global + local)

    for (int st = qt; st >= 0; --st) {
        int s0 = st * 64;
        bool inwin = (st >= wt0);
        if (!inwin) {
            float dend = D[h * T_SEQ + s0 + 63];
            if (dq0 - dend < -88.f) break;
        }
        __syncthreads();   // protect K/V/Ph vs previous PV reads

        load_split_tile(P + (size_t)s0 * PSTR + KOFF + kvh * DHD, sb + OFF_K, sb + OFF_K + 8192u, tid);
        load_split_tile(P + (size_t)s0 * PSTR + VOFF + kvh * DHD, sb + OFF_V, sb + OFF_V + 8192u, tid);
        if (tid < 64) {
            float ds = D[h * T_SEQ + s0 + tid];
            float ls = L[h * T_SEQ + s0 + tid];
            Ds[tid] = ds; Ls[tid] = ls;
            colE[tid] = expf(dq0 - ds + ls);
        }
        __syncthreads();

        // ---- S = Q @ K^T (bf16x3) ----
        float sacc[4][4] = {};
        {
            int arow = wm * 16 + (lane & 15);
            int asel = lane >> 4;
            int nrow = wn * 32 + (lane & 7) + ((lane >> 4) << 3);
            int bsel = (lane >> 3) & 1;
#pragma unroll
            for (int ks = 0; ks < 4; ks++) {
                uint32_t ah[4], al[4];
                uint32_t abase = sb + OFF_Q + (uint32_t)arow * 128u;
                ah[0] = 0;
                ldsm4(ah, abase + (uint32_t)(((2 * ks + asel) ^ (arow & 7)) * 16));
                ldsm4(al, abase + 8192u + (uint32_t)(((2 * ks + asel) ^ (arow & 7)) * 16));
                uint32_t bh[2][4], bl[2][4];
#pragma unroll
                for (int g = 0; g < 2; g++) {
                    int r = nrow + g * 16;
                    uint32_t bbase = sb + OFF_K + (uint32_t)r * 128u;
                    ldsm4(bh[g], bbase + (uint32_t)(((2 * ks + bsel) ^ (r & 7)) * 16));
                    ldsm4(bl[g], bbase + 8192u + (uint32_t)(((2 * ks + bsel) ^ (r & 7)) * 16));
                }
#pragma unroll
                for (int j = 0; j < 4; j++) {
                    const uint32_t* b2h = &bh[j >> 1][2 * (j & 1)];
                    const uint32_t* b2l = &bl[j >> 1][2 * (j & 1)];
                    mma_bf16(sacc[j], ah, b2h);
                    mma_bf16(sacc[j], ah, b2l);
                    mma_bf16(sacc[j], al, b2h);
                }
            }
        }
        __syncthreads();   // QK reads of K done before Ph overwrites K region

        // ---- weight, stash local scores, split P -> smem ----
        {
            int colbase = s0 - w0;
#pragma unroll
            for (int j = 0; j < 4; j++) {
                int cj = fcb + 8 * j;
#pragma unroll
                for (int half = 0; half < 2; half++) {
                    int r = fr0 + half * 8;
                    float v0 = sacc[j][2 * half], v1 = sacc[j][2 * half + 1];
                    // local stash
                    if (inwin) {
                        float l0 = (s0 + cj     <= t0 + r) ? v0 * 0.125f : neg_inf();
                        float l1 = (s0 + cj + 1 <= t0 + r) ? v1 * 0.125f : neg_inf();
                        *reinterpret_cast<float2*>(&smS[r * SSTR + colbase + cj]) = make_float2(l0, l1);
                    }
                    // global weight
                    float p0, p1;
                    if (st == qt) {
                        p0 = (cj     <= r) ? v0 * expf(Dq[r] - Ds[cj] + Ls[cj]) : 0.f;
                        p1 = (cj + 1 <= r) ? v1 * expf(Dq[r] - Ds[cj + 1] + Ls[cj + 1]) : 0.f;
                    } else {
                        float re = rowE[r];
                        p0 = v0 * (re * colE[cj]);
                        p1 = v1 * (re * colE[cj + 1]);
                    }
                    float h0 = __bfloat162float(__float2bfloat16_rn(p0));
                    float h1 = __bfloat162float(__float2bfloat16_rn(p1));
                    uint32_t phys = (uint32_t)r * 128u + (uint32_t)((((cj >> 3)) ^ (r & 7)) * 16) + (uint32_t)((cj & 7) * 2);
                    sts4(sb + OFF_K + phys, pack2bf(h0, h1));
                    sts4(sb + OFF_K + 8192u + phys, pack2bf(p0 - h0, p1 - h1));
                }
            }
        }
        __syncthreads();

        // ---- O += P @ V (bf16x3, V^T via ldmatrix.trans) ----
        {
            int arow = wm * 16 + (lane & 15);
            int asel = lane >> 4;
#pragma unroll
            for (int ks = 0; ks < 4; ks++) {
                uint32_t ph[4], pl[4];
                uint32_t abase = sb + OFF_K + (uint32_t)arow * 128u;
                ldsm4(ph, abase + (uint32_t)(((2 * ks + asel) ^ (arow & 7)) * 16));
                ldsm4(pl, abase + 8192u + (uint32_t)(((2 * ks + asel) ^ (arow & 7)) * 16));
                int vrow = ks * 16 + (lane & 15);
                uint32_t vb = sb + OFF_V + (uint32_t)vrow * 128u;
                uint32_t vh[2][4], vl[2][4];
#pragma unroll
                for (int g = 0; g < 2; g++) {
                    int cch = wn * 4 + 2 * g + (lane >> 4);
                    ldsm4t(vh[g], vb + (uint32_t)((cch ^ (vrow & 7)) * 16));
                    ldsm4t(vl[g], vb + 8192u + (uint32_t)((cch ^ (vrow & 7)) * 16));
                }
#pragma unroll
                for (int j = 0; j < 4; j++) {
                    const uint32_t* b2h = &vh[j >> 1][2 * (j & 1)];
                    const uint32_t* b2l = &vl[j >> 1][2 * (j & 1)];
                    mma_bf16(oacc[j], ph, b2h);
                    mma_bf16(oacc[j], ph, b2l);
                    mma_bf16(oacc[j], pl, b2h);
                }
            }
        }
    }

    // ================= local window path =================
    __syncthreads();
    // softmax over Ss rows (nk cols), 4 lanes per row
    {
        int r = tid >> 2, g = tid & 3;
        float m = neg_inf();
        for (int c = g; c < nk; c += 4) m = fmaxf(m, smS[r * SSTR + c]);
        m = fmaxf(m, __shfl_xor_sync(0xffffffff, m, 1));
        m = fmaxf(m, __shfl_xor_sync(0xffffffff, m, 2));
        float sum = 0.f;
        for (int c = g; c < nk; c += 4) {
            float e = expf(smS[r * SSTR + c] - m);
            smS[r * SSTR + c] = e;
            sum += e;
        }
        sum += __shfl_xor_sync(0xffffffff, sum, 1);
        sum += __shfl_xor_sync(0xffffffff, sum, 2);
        float inv = 1.f / sum;
        for (int c = g; c < nk; c += 4) smS[r * SSTR + c] *= inv;
    }
    __syncthreads();

    for (int kh = 0; kh < (nk >> 6); kh++) {
        // V window tile into stream buffer; P half split into Ph/Pl (K region)
        load_split_tile(P + (size_t)(w0 + kh * 64) * PSTR + VOFF + kvh * DHD, sb + OFF_V, sb + OFF_V + 8192u, tid);
#pragma unroll
        for (int i = 0; i < 8; i++) {
            int idx = tid + i * 256;
            int r = idx >> 5, c2 = idx & 31;
            float2 v = *reinterpret_cast<const float2*>(&smS[r * SSTR + kh * 64 + 2 * c2]);
            float h0 = __bfloat162float(__float2bfloat16_rn(v.x));
            float h1 = __bfloat162float(__float2bfloat16_rn(v.y));
            uint32_t phys = (uint32_t)r * 128u + (uint32_t)((((c2 >> 2)) ^ (r & 7)) * 16) + (uint32_t)((c2 & 3) * 4);
            sts4(sb + OFF_K + phys, pack2bf(h0, h1));
            sts4(sb + OFF_K + 8192u + phys, pack2bf(v.x - h0, v.y - h1));
        }
        __syncthreads();
        {
            int arow = wm * 16 + (lane & 15);
            int asel = lane >> 4;
#pragma unroll
            for (int ks = 0; ks < 4; ks++) {
                uint32_t ph[4], pl[4];
                uint32_t abase = sb + OFF_K + (uint32_t)arow * 128u;
                ldsm4(ph, abase + (uint32_t)(((2 * ks + asel) ^ (arow & 7)) * 16));
                ldsm4(pl, abase + 8192u + (uint32_t)(((2 * ks + asel) ^ (arow & 7)) * 16));
                int vrow = ks * 16 + (lane & 15);
                uint32_t vb = sb + OFF_V + (uint32_t)vrow * 128u;
                uint32_t vh[2][4], vl[2][4];
#pragma unroll
                for (int g = 0; g < 2; g++) {
                    int cch = wn * 4 + 2 * g + (lane >> 4);
                    ldsm4t(vh[g], vb + (uint32_t)((cch ^ (vrow & 7)) * 16));
                    ldsm4t(vl[g], vb + 8192u + (uint32_t)((cch ^ (vrow & 7)) * 16));
                }
#pragma unroll
                for (int j = 0; j < 4; j++) {
                    const uint32_t* b2h = &vh[j >> 1][2 * (j & 1)];
                    const uint32_t* b2l = &vl[j >> 1][2 * (j & 1)];
                    mma_bf16(oacc[j], ph, b2h);
                    mma_bf16(oacc[j], ph, b2l);
                    mma_bf16(oacc[j], pl, b2h);
                }
            }
        }
        __syncthreads();   // before next V/P overwrite
    }

    // ---- write Y ----
#pragma unroll
    for (int j = 0; j < 4; j++) {
        int col = h * DHD + fcb + 8 * j;
        *reinterpret_cast<float2*>(Y + (size_t)(t0 + fr0) * C_DIM + col) = make_float2(oacc[j][0], oacc[j][1]);
        *reinterpret_cast<float2*>(Y + (size_t)(t0 + fr0 + 8) * C_DIM + col) = make_float2(oacc[j][2], oacc[j][3]);
    }
}

// ---------------- gate logits ----------------
__global__ __launch_bounds__(256) void gate_kernel(
    const float* __restrict__ x, const float* __restrict__ Wg,
    const float* __restrict__ bg, float* __restrict__ G)
{
    __shared__ float xs[C_DIM];
    __shared__ float red[16][17];
    int t = blockIdx.x, tid = threadIdx.x;
    float4 v = *reinterpret_cast<const float4*>(x + (size_t)t * C_DIM + tid * 4);
    xs[tid * 4 + 0] = v.x; xs[tid * 4 + 1] = v.y;
    xs[tid * 4 + 2] = v.z; xs[tid * 4 + 3] = v.w;
    __syncthreads();
    int h = tid & 15, part = tid >> 4;
    float s = 0.f;
#pragma unroll 8
    for (int i = 0; i < 64; i++) {
        int c = part * 64 + i;
        s += xs[c] * Wg[c * NH + h];
    }
    red[part][h] = s;
    __syncthreads();
    if (tid < 16) {
        float acc = bg[tid];
#pragma unroll
        for (int p = 0; p < 16; p++) acc += red[p][tid];
        G[tid * T_SEQ + t] = acc;
    }
}

// ---------------- per-head scan ----------------
__global__ __launch_bounds__(256) void scan_kernel(
    const float* __restrict__ G, float* __restrict__ D, float* __restrict__ L)
{
    int h = blockIdx.x, tid = threadIdx.x;
    const float* g = G + h * T_SEQ;
    float vals[8];
    float run = 0.f;
#pragma unroll
    for (int i = 0; i < 8; i++) {
        float gg = g[tid * 8 + i];
        run += log_sigmoid_f(gg);
        vals[i] = run;
        L[h * T_SEQ + tid * 8 + i] = log_sigmoid_f(-gg);
    }
    __shared__ float s[256];
    s[tid] = run;
    __syncthreads();
    for (int off = 1; off < 256; off <<= 1) {
        float v = 0.f;
        if (tid >= off) v = s[tid - off];
        __syncthreads();
        s[tid] += v;
        __syncthreads();
    }
    float excl = s[tid] - run;
#pragma unroll
    for (int i = 0; i < 8; i++) D[h * T_SEQ + tid * 8 + i] = vals[i] + excl;
}

// ---------------- RoPE ----------------
__global__ __launch_bounds__(256) void rope_kernel(float* __restrict__ P, int heads, int stride, int colOff)
{
    int idx = blockIdx.x * blockDim.x + threadIdx.x;
    int total = T_SEQ * heads * 32;
    if (idx >= total) return;
    int d = idx & 31;
    int h = (idx >> 5) % heads;
    int t = idx / (heads * 32);
    float inv = expf(-(float)(2 * d) * (9.210340371976184f / 64.f));
    float theta = (float)t * inv;
    float sn, cs;
    sincosf(theta, &sn, &cs);
    float* p = P + (size_t)t * stride + colOff + h * DHD;
    float a = p[d], b = p[d + 32];
    p[d]      = a * cs - b * sn;
    p[d + 32] = b * cs + a * sn;
}

// ---------------- RMSNorm ----------------
__global__ __launch_bounds__(256) void rmsnorm_kernel(float* __restrict__ Y, const float* __restrict__ w)
{
    int t = blockIdx.x, tid = threadIdx.x;
    float4* yp = reinterpret_cast<float4*>(Y + (size_t)t * C_DIM + tid * 4);
    float4 v = *yp;
    float ss = v.x * v.x + v.y * v.y + v.z * v.z + v.w * v.w;
#pragma unroll
    for (int off = 16; off; off >>= 1) ss += __shfl_xor_sync(0xffffffff, ss, off);
    __shared__ float red[8];
    if ((tid & 31) == 0) red[tid >> 5] = ss;
    __syncthreads();
    if (tid < 8) {
        float s = red[tid];
        s += __shfl_xor_sync(0xff, s, 1);
        s += __shfl_xor_sync(0xff, s, 2);
        s += __shfl_xor_sync(0xff, s, 4);
        if (tid == 0) red[0] = s;
    }
    __syncthreads();
    float scale = rsqrtf(red[0] * (1.f / (float)C_DIM) + 1e-5f);
    float4 wv = *reinterpret_cast<const float4*>(w + tid * 4);
    v.x *= scale * wv.x; v.y *= scale * wv.y; v.z *= scale * wv.z; v.w *= scale * wv.w;
    *yp = v;
}

// ---------------- launch ----------------
extern "C" void kernel_launch(void* const* d_in, const int* in_sizes, int n_in,
                              void* d_out, int out_size)
{
    (void)in_sizes; (void)n_in; (void)out_size;
    const float* x    = (const float*)d_in[0];
    const float* Wq   = (const float*)d_in[1];
    const float* Wk   = (const float*)d_in[2];
    const float* Wv   = (const float*)d_in[3];
    const float* Wc   = (const float*)d_in[4];
    const float* Wg   = (const float*)d_in[5];
    const float* bg   = (const float*)d_in[6];
    const float* rmsw = (const float*)d_in[7];
    float* out = (float*)d_out;

    float *P, *G, *D, *L, *Y;
    __nv_bfloat16 *Wph, *Wpl, *Wch, *Wcl;
    cudaGetSymbolAddress((void**)&P, g_P);
    cudaGetSymbolAddress((void**)&G, g_G);
    cudaGetSymbolAddress((void**)&D, g_D);
    cudaGetSymbolAddress((void**)&L, g_L);
    cudaGetSymbolAddress((void**)&Y, g_Y);
    cudaGetSymbolAddress((void**)&Wph, g_Wp_h);
    cudaGetSymbolAddress((void**)&Wpl, g_Wp_l);
    cudaGetSymbolAddress((void**)&Wch, g_Wc_h);
    cudaGetSymbolAddress((void**)&Wcl, g_Wc_l);

    const int KD = C_DIM;

    transpose_split<<<dim3(C_DIM / 32, KD / 32), 256>>>(Wq, Wph, Wpl, KD, C_DIM);
    transpose_split<<<dim3(256 / 32, KD / 32), 256>>>(Wk, Wph + (size_t)KOFF * KD, Wpl + (size_t)KOFF * KD, KD, 256);
    transpose_split<<<dim3(256 / 32, KD / 32), 256>>>(Wv, Wph + (size_t)VOFF * KD, Wpl + (size_t)VOFF * KD, KD, 256);
    transpose_split<<<dim3(C_DIM / 32, KD / 32), 256>>>(Wc, Wch, Wcl, KD, C_DIM);

    size_t smemTC = 65536;
    cudaFuncSetAttribute(gemm_mma, cudaFuncAttributeMaxDynamicSharedMemorySize, (int)smemTC);
    gemm_mma<<<dim3(PSTR / 128, T_SEQ / 128), 256, smemTC>>>(x, Wph, Wpl, P, T_SEQ, PSTR, KD);

    gate_kernel<<<T_SEQ, 256>>>(x, Wg, bg, G);
    scan_kernel<<<NH, 256>>>(G, D, L);

    rope_kernel<<<(T_SEQ * NH * 32 + 255) / 256, 256>>>(P, NH, PSTR, 0);
    rope_kernel<<<(T_SEQ * NKV * 32 + 255) / 256, 256>>>(P, NKV, PSTR, KOFF);

    size_t smemA = OFF_SC + 6 * 64 * sizeof(float);
    cudaFuncSetAttribute(attn_fused, cudaFuncAttributeMaxDynamicSharedMemorySize, (int)smemA);
    attn_fused<<<dim3(T_SEQ / 64, NH), 256, smemA>>>(P, D, L, Y);

    rmsnorm_kernel<<<T_SEQ, 256>>>(Y, rmsw);
    gemm_mma<<<dim3(C_DIM / 128, T_SEQ / 128), 256, smemTC>>>(Y, Wch, Wcl, out, T_SEQ, C_DIM, KD);
}

// round 5
// speedup vs baseline: 2.4989x; 1.0890x over previous
#include <cuda_runtime.h>
#include <cuda_bf16.h>
#include <math.h>
#include <stdint.h>

#define T_SEQ 2048
#define C_DIM 1024
#define NH    16
#define NKV   4
#define DHD   64
#define WINSZ 128
#define PSTR  1664          /* fused projection row stride: Q(1024) | K(256) | V(256) | gate(16 + 112 pad) */
#define KOFF  1024
#define VOFF  1280
#define GOFF  1536

// ---------------- scratch (no allocations allowed) ----------------
__device__ float g_P[T_SEQ * PSTR];          // fused Q|K|V|gate projections
__device__ float g_D[NH * T_SEQ];
__device__ float g_L[NH * T_SEQ];
__device__ float g_Y[T_SEQ * C_DIM];
__device__ float g_scale[T_SEQ];
__device__ __nv_bfloat16 g_Wp_h[PSTR * C_DIM];   // transposed split proj weights [N][K] (pad rows stay 0)
__device__ __nv_bfloat16 g_Wp_l[PSTR * C_DIM];
__device__ __nv_bfloat16 g_Wc_h[C_DIM * C_DIM];
__device__ __nv_bfloat16 g_Wc_l[C_DIM * C_DIM];

__device__ __forceinline__ float neg_inf() { return __int_as_float(0xff800000); }
__device__ __forceinline__ float log_sigmoid_f(float x) {
    return fminf(x, 0.f) - log1pf(expf(-fabsf(x)));
}
__device__ __forceinline__ uint32_t cvta_smem(const void* p) {
    uint32_t a;
    asm("{ .reg .u64 t; cvta.to.shared.u64 t, %1; cvt.u32.u64 %0, t; }" : "=r"(a) : "l"(p));
    return a;
}
__device__ __forceinline__ uint32_t pack2bf(float a, float b) {
    __nv_bfloat162 t = __floats2bfloat162_rn(a, b);
    return *reinterpret_cast<uint32_t*>(&t);
}
__device__ __forceinline__ void ldsm4(uint32_t* r, uint32_t addr) {
    asm volatile("ldmatrix.sync.aligned.m8n8.x4.shared.b16 {%0,%1,%2,%3}, [%4];"
                 : "=r"(r[0]), "=r"(r[1]), "=r"(r[2]), "=r"(r[3]) : "r"(addr));
}
__device__ __forceinline__ void ldsm4t(uint32_t* r, uint32_t addr) {
    asm volatile("ldmatrix.sync.aligned.m8n8.x4.trans.shared.b16 {%0,%1,%2,%3}, [%4];"
                 : "=r"(r[0]), "=r"(r[1]), "=r"(r[2]), "=r"(r[3]) : "r"(addr));
}
__device__ __forceinline__ void mma_bf16(float* c, const uint32_t* a, const uint32_t* b) {
    asm volatile(
        "mma.sync.aligned.m16n8k16.row.col.f32.bf16.bf16.f32 "
        "{%0,%1,%2,%3}, {%4,%5,%6,%7}, {%8,%9}, {%0,%1,%2,%3};"
        : "+f"(c[0]), "+f"(c[1]), "+f"(c[2]), "+f"(c[3])
        : "r"(a[0]), "r"(a[1]), "r"(a[2]), "r"(a[3]), "r"(b[0]), "r"(b[1]));
}
__device__ __forceinline__ void sts16(uint32_t addr, uint32_t a, uint32_t b, uint32_t c, uint32_t d) {
    asm volatile("st.shared.v4.b32 [%0], {%1,%2,%3,%4};" :: "r"(addr), "r"(a), "r"(b), "r"(c), "r"(d) : "memory");
}
__device__ __forceinline__ void sts8(uint32_t addr, uint32_t a, uint32_t b) {
    asm volatile("st.shared.v2.b32 [%0], {%1,%2};" :: "r"(addr), "r"(a), "r"(b) : "memory");
}
__device__ __forceinline__ void sts4(uint32_t addr, uint32_t a) {
    asm volatile("st.shared.b32 [%0], %1;" :: "r"(addr), "r"(a) : "memory");
}

// load 64x64 fp32 tile -> split bf16 hi/lo into swizzled smem (128B rows)
__device__ __forceinline__ void load_split_tile(
    const float* __restrict__ gsrc, uint32_t smH, uint32_t smL, int tid)
{
#pragma unroll
    for (int i = 0; i < 4; i++) {
        int f = tid + i * 256;
        int r = f >> 4, q4 = f & 15;
        float4 v = *reinterpret_cast<const float4*>(gsrc + (size_t)r * PSTR + q4 * 4);
        float hx = __bfloat162float(__float2bfloat16_rn(v.x));
        float hy = __bfloat162float(__float2bfloat16_rn(v.y));
        float hz = __bfloat162float(__float2bfloat16_rn(v.z));
        float hw = __bfloat162float(__float2bfloat16_rn(v.w));
        uint32_t phys = (uint32_t)r * 128u + (uint32_t)(((q4 >> 1) ^ (r & 7)) * 16) + (uint32_t)((q4 & 1) * 8);
        sts8(smH + phys, pack2bf(hx, hy), pack2bf(hz, hw));
        sts8(smL + phys, pack2bf(v.x - hx, v.y - hy), pack2bf(v.z - hz, v.w - hw));
    }
}

// ---------------- merged weight transpose + bf16 split ----------------
// z=0: Wq -> Wp rows 0..1023; z=1: Wk -> rows 1024..; z=2: Wv -> rows 1280..;
// z=3: Wc*rmsw -> Wc arrays.
__global__ __launch_bounds__(256) void transpose_split_all(
    const float* __restrict__ Wq, const float* __restrict__ Wk,
    const float* __restrict__ Wv, const float* __restrict__ Wc,
    const float* __restrict__ rmsw,
    __nv_bfloat16* __restrict__ Wph, __nv_bfloat16* __restrict__ Wpl,
    __nv_bfloat16* __restrict__ Wch, __nv_bfloat16* __restrict__ Wcl)
{
    int z = blockIdx.z;
    const float* W; __nv_bfloat16 *Th, *Tl; int N, rowOff = 0; bool useScale = false;
    if (z == 0)      { W = Wq; Th = Wph; Tl = Wpl; N = 1024; }
    else if (z == 1) { W = Wk; Th = Wph; Tl = Wpl; N = 256; rowOff = KOFF; }
    else if (z == 2) { W = Wv; Th = Wph; Tl = Wpl; N = 256; rowOff = VOFF; }
    else             { W = Wc; Th = Wch; Tl = Wcl; N = 1024; useScale = true; }
    int n0 = blockIdx.x * 32;
    if (n0 >= N) return;
    int k0 = blockIdx.y * 32;

    __shared__ float s[32][33];
    int tx = threadIdx.x & 31, ty = threadIdx.x >> 5;
#pragma unroll
    for (int i = 0; i < 4; i++) {
        int r = ty + i * 8;
        float v = W[(size_t)(k0 + r) * N + n0 + tx];
        if (useScale) v *= rmsw[k0 + r];
        s[r][tx] = v;
    }
    __syncthreads();
#pragma unroll
    for (int i = 0; i < 4; i++) {
        int r = ty + i * 8;
        float v = s[tx][r];
        __nv_bfloat16 h = __float2bfloat16_rn(v);
        Th[(size_t)(rowOff + n0 + r) * C_DIM + k0 + tx] = h;
        Tl[(size_t)(rowOff + n0 + r) * C_DIM + k0 + tx] = __float2bfloat16_rn(v - __bfloat162float(h));
    }
}

// gate weight [C,16] -> Wp rows GOFF..GOFF+15 (transposed, split)
__global__ __launch_bounds__(256) void gate_wsplit(
    const float* __restrict__ Wg, __nv_bfloat16* __restrict__ Th, __nv_bfloat16* __restrict__ Tl)
{
    int i = blockIdx.x * 256 + threadIdx.x;      // 16384 total
    int c = i >> 4, h = i & 15;
    float v = Wg[c * NH + h];
    __nv_bfloat16 hh = __float2bfloat16_rn(v);
    Th[(size_t)(GOFF + h) * C_DIM + c] = hh;
    Tl[(size_t)(GOFF + h) * C_DIM + c] = __float2bfloat16_rn(v - __bfloat162float(hh));
}

// ---------------- bf16x3 tensor-core GEMM (+optional row scaling, +optional RoPE epilogue) ----------------
__global__ __launch_bounds__(256, 1) void gemm_mma(
    const float* __restrict__ A, const __nv_bfloat16* __restrict__ Bh,
    const __nv_bfloat16* __restrict__ Bl, float* __restrict__ C,
    int M, int N, int K, const float* __restrict__ rowScale, int doRope)
{
    extern __shared__ char smc[];
    uint32_t sb = cvta_smem(smc);

    int tid = threadIdx.x, lane = tid & 31, warp = tid >> 5;
    int wm = warp & 3, wn = warp >> 2;
    int m0 = blockIdx.y * 128, n0 = blockIdx.x * 128;

    int row = tid & 127;
    bool isB = tid >= 128;
    const float* ag = A + (size_t)(m0 + row) * K;
    const __nv_bfloat16* bhg = Bh + (size_t)(n0 + row) * K;
    const __nv_bfloat16* blg = Bl + (size_t)(n0 + row) * K;
    float rs = (!isB && rowScale) ? rowScale[m0 + row] : 1.0f;

    float acc[2][8][4] = {};
    float4 pa[8];
    uint4 pbh[4], pbl[4];

    if (!isB) {
#pragma unroll
        for (int i = 0; i < 8; i++) pa[i] = *reinterpret_cast<const float4*>(ag + i * 4);
    } else {
#pragma unroll
        for (int c = 0; c < 4; c++) {
            pbh[c] = *reinterpret_cast<const uint4*>(bhg + c * 8);
            pbl[c] = *reinterpret_cast<const uint4*>(blg + c * 8);
        }
    }

    int nkt = K / 32;
    for (int kt = 0; kt < nkt; ++kt) {
        uint32_t stage = sb + (uint32_t)(kt & 1) * 32768u;
        uint32_t aB = stage, bB = stage + 16384u;

        if (!isB) {
            uint32_t dst = aB + (uint32_t)row * 128u;
            int rsw = row & 7;
#pragma unroll
            for (int c = 0; c < 4; c++) {
                float4 v0 = pa[2 * c], v1 = pa[2 * c + 1];
                v0.x *= rs; v0.y *= rs; v0.z *= rs; v0.w *= rs;
                v1.x *= rs; v1.y *= rs; v1.z *= rs; v1.w *= rs;
                float h0 = __bfloat162float(__float2bfloat16_rn(v0.x));
                float h1 = __bfloat162float(__float2bfloat16_rn(v0.y));
                float h2 = __bfloat162float(__float2bfloat16_rn(v0.z));
                float h3 = __bfloat162float(__float2bfloat16_rn(v0.w));
                float h4 = __bfloat162float(__float2bfloat16_rn(v1.x));
                float h5 = __bfloat162float(__float2bfloat16_rn(v1.y));
                float h6 = __bfloat162float(__float2bfloat16_rn(v1.z));
                float h7 = __bfloat162float(__float2bfloat16_rn(v1.w));
                sts16(dst + (uint32_t)((c ^ rsw) * 16),
                      pack2bf(h0, h1), pack2bf(h2, h3), pack2bf(h4, h5), pack2bf(h6, h7));
                sts16(dst + (uint32_t)(((4 + c) ^ rsw) * 16),
                      pack2bf(v0.x - h0, v0.y - h1), pack2bf(v0.z - h2, v0.w - h3),
                      pack2bf(v1.x - h4, v1.y - h5), pack2bf(v1.z - h6, v1.w - h7));
            }
        } else {
            uint32_t dst = bB + (uint32_t)row * 128u;
            int rsw = row & 7;
#pragma unroll
            for (int c = 0; c < 4; c++) {
                sts16(dst + (uint32_t)((c ^ rsw) * 16), pbh[c].x, pbh[c].y, pbh[c].z, pbh[c].w);
                sts16(dst + (uint32_t)(((4 + c) ^ rsw) * 16), pbl[c].x, pbl[c].y, pbl[c].z, pbl[c].w);
            }
        }
        __syncthreads();

        if (kt + 1 < nkt) {
            int kb = (kt + 1) * 32;
            if (!isB) {
#pragma unroll
                for (int i = 0; i < 8; i++) pa[i] = *reinterpret_cast<const float4*>(ag + kb + i * 4);
            } else {
#pragma unroll
                for (int c = 0; c < 4; c++) {
                    pbh[c] = *reinterpret_cast<const uint4*>(bhg + kb + c * 8);
                    pbl[c] = *reinterpret_cast<const uint4*>(blg + kb + c * 8);
                }
            }
        }

#pragma unroll
        for (int s = 0; s < 2; s++) {
            uint32_t ahi[2][4], alo[2][4];
            int arow = wm * 32 + (lane & 15);
            int asel = lane >> 4;
#pragma unroll
            for (int t = 0; t < 2; t++) {
                int r = arow + t * 16;
                uint32_t base = aB + (uint32_t)r * 128u;
                ldsm4(ahi[t], base + (uint32_t)((((2 * s) + asel) ^ (r & 7)) * 16));
                ldsm4(alo[t], base + (uint32_t)(((4 + 2 * s + asel) ^ (r & 7)) * 16));
            }
            uint32_t bhi[4][4], blo[4][4];
            int nrow = wn * 64 + (lane & 7) + ((lane >> 4) << 3);
            int bsel = (lane >> 3) & 1;
#pragma unroll
            for (int g = 0; g < 4; g++) {
                int r = nrow + g * 16;
                uint32_t base = bB + (uint32_t)r * 128u;
                ldsm4(bhi[g], base + (uint32_t)((((2 * s) + bsel) ^ (r & 7)) * 16));
                ldsm4(blo[g], base + (uint32_t)(((4 + 2 * s + bsel) ^ (r & 7)) * 16));
            }
#pragma unroll
            for (int t = 0; t < 2; t++)
#pragma unroll
                for (int j = 0; j < 8; j++) {
                    const uint32_t* bh2 = &bhi[j >> 1][2 * (j & 1)];
                    const uint32_t* bl2 = &blo[j >> 1][2 * (j & 1)];
                    mma_bf16(acc[t][j], ahi[t], bh2);
                    mma_bf16(acc[t][j], ahi[t], bl2);
                    mma_bf16(acc[t][j], alo[t], bh2);
                }
        }
    }

    // ---- RoPE epilogue (proj GEMM only; warp slice = one 64-wide head, j & j+4 are the (d,d+32) pair) ----
    if (doRope && (n0 + wn * 64) < 1280) {
#pragma unroll
        for (int j = 0; j < 4; j++) {
#pragma unroll
            for (int e = 0; e < 2; e++) {
                int d = j * 8 + 2 * (lane & 3) + e;
                float invf = expf(-(float)(2 * d) * (9.210340371976184f / 64.f));
#pragma unroll
                for (int mt = 0; mt < 2; mt++) {
#pragma unroll
                    for (int rh = 0; rh < 2; rh++) {
                        int trow = m0 + wm * 32 + mt * 16 + (lane >> 2) + rh * 8;
                        float sn, cs;
                        sincosf((float)trow * invf, &sn, &cs);
                        int k = 2 * rh + e;
                        float a = acc[mt][j][k], b = acc[mt][j + 4][k];
                        acc[mt][j][k]     = a * cs - b * sn;
                        acc[mt][j + 4][k] = b * cs + a * sn;
                    }
                }
            }
        }
    }

#pragma unroll
    for (int t = 0; t < 2; t++) {
        int r0 = m0 + wm * 32 + t * 16 + (lane >> 2);
#pragma unroll
        for (int j = 0; j < 8; j++) {
            int col = n0 + wn * 64 + j * 8 + 2 * (lane & 3);
            *reinterpret_cast<float2*>(C + (size_t)r0 * N + col) = make_float2(acc[t][j][0], acc[t][j][1]);
            *reinterpret_cast<float2*>(C + (size_t)(r0 + 8) * N + col) = make_float2(acc[t][j][2], acc[t][j][3]);
        }
    }
}

// ---------------- per-head scan (reads gate logits from P, adds bias) ----------------
__global__ __launch_bounds__(256) void scan_kernel(
    const float* __restrict__ P, const float* __restrict__ bg,
    float* __restrict__ D, float* __restrict__ L)
{
    int h = blockIdx.x, tid = threadIdx.x;
    float b = bg[h];
    float vals[8];
    float run = 0.f;
#pragma unroll
    for (int i = 0; i < 8; i++) {
        int t = tid * 8 + i;
        float gg = P[(size_t)t * PSTR + GOFF + h] + b;
        run += log_sigmoid_f(gg);
        vals[i] = run;
        L[h * T_SEQ + t] = log_sigmoid_f(-gg);
    }
    __shared__ float s[256];
    s[tid] = run;
    __syncthreads();
    for (int off = 1; off < 256; off <<= 1) {
        float v = 0.f;
        if (tid >= off) v = s[tid - off];
        __syncthreads();
        s[tid] += v;
        __syncthreads();
    }
    float excl = s[tid] - run;
#pragma unroll
    for (int i = 0; i < 8; i++) D[h * T_SEQ + tid * 8 + i] = vals[i] + excl;
}

// ---------------- fused global-decay + local-window attention (tensor cores) ----------------
#define OFF_Q  0u
#define OFF_K  16384u
#define OFF_V  32768u
#define OFF_S  49152u
#define SSTR   132
#define OFF_SC (49152u + 64u * SSTR * 4u)

__global__ __launch_bounds__(256, 2) void attn_fused(
    const float* __restrict__ P, const float* __restrict__ D,
    const float* __restrict__ L, float* __restrict__ Y)
{
    extern __shared__ char smc[];
    uint32_t sb = cvta_smem(smc);
    float* smS  = reinterpret_cast<float*>(smc + OFF_S);
    float* Dq   = reinterpret_cast<float*>(smc + OFF_SC);
    float* rowE = Dq + 64;
    float* Ds   = rowE + 64;
    float* Ls   = Ds + 64;
    float* colE = Ls + 64;

    int qt = blockIdx.x, h = blockIdx.y;
    int kvh = h >> 2;
    int tid = threadIdx.x, lane = tid & 31, warp = tid >> 5;
    int wm = warp & 3, wn = warp >> 2;
    int t0 = qt * 64;
    int w0 = (t0 / WINSZ) * WINSZ;
    int wt0 = w0 / 64;
    int nk = t0 - w0 + 64;

    load_split_tile(P + (size_t)t0 * PSTR + h * DHD, sb + OFF_Q, sb + OFF_Q + 8192u, tid);
    if (tid < 64) Dq[tid] = D[h * T_SEQ + t0 + tid];
    __syncthreads();
    float dq0 = Dq[0];
    if (tid < 64) rowE[tid] = expf(Dq[tid] - dq0);

    int fr0 = wm * 16 + (lane >> 2);
    int fcb = wn * 32 + 2 * (lane & 3);

    float oacc[4][4] = {};

    for (int st = qt; st >= 0; --st) {
        int s0 = st * 64;
        bool inwin = (st >= wt0);
        if (!inwin) {
            float dend = D[h * T_SEQ + s0 + 63];
            if (dq0 - dend < -88.f) break;
        }
        __syncthreads();

        load_split_tile(P + (size_t)s0 * PSTR + KOFF + kvh * DHD, sb + OFF_K, sb + OFF_K + 8192u, tid);
        load_split_tile(P + (size_t)s0 * PSTR + VOFF + kvh * DHD, sb + OFF_V, sb + OFF_V + 8192u, tid);
        if (tid < 64) {
            float ds = D[h * T_SEQ + s0 + tid];
            float ls = L[h * T_SEQ + s0 + tid];
            Ds[tid] = ds; Ls[tid] = ls;
            colE[tid] = expf(dq0 - ds + ls);
        }
        __syncthreads();

        float sacc[4][4] = {};
        {
            int arow = wm * 16 + (lane & 15);
            int asel = lane >> 4;
            int nrow = wn * 32 + (lane & 7) + ((lane >> 4) << 3);
            int bsel = (lane >> 3) & 1;
#pragma unroll
            for (int ks = 0; ks < 4; ks++) {
                uint32_t ah[4], al[4];
                uint32_t abase = sb + OFF_Q + (uint32_t)arow * 128u;
                ldsm4(ah, abase + (uint32_t)(((2 * ks + asel) ^ (arow & 7)) * 16));
                ldsm4(al, abase + 8192u + (uint32_t)(((2 * ks + asel) ^ (arow & 7)) * 16));
                uint32_t bh[2][4], bl[2][4];
#pragma unroll
                for (int g = 0; g < 2; g++) {
                    int r = nrow + g * 16;
                    uint32_t bbase = sb + OFF_K + (uint32_t)r * 128u;
                    ldsm4(bh[g], bbase + (uint32_t)(((2 * ks + bsel) ^ (r & 7)) * 16));
                    ldsm4(bl[g], bbase + 8192u + (uint32_t)(((2 * ks + bsel) ^ (r & 7)) * 16));
                }
#pragma unroll
                for (int j = 0; j < 4; j++) {
                    const uint32_t* b2h = &bh[j >> 1][2 * (j & 1)];
                    const uint32_t* b2l = &bl[j >> 1][2 * (j & 1)];
                    mma_bf16(sacc[j], ah, b2h);
                    mma_bf16(sacc[j], ah, b2l);
                    mma_bf16(sacc[j], al, b2h);
                }
            }
        }
        __syncthreads();

        {
            int colbase = s0 - w0;
#pragma unroll
            for (int j = 0; j < 4; j++) {
                int cj = fcb + 8 * j;
#pragma unroll
                for (int half = 0; half < 2; half++) {
                    int r = fr0 + half * 8;
                    float v0 = sacc[j][2 * half], v1 = sacc[j][2 * half + 1];
                    if (inwin) {
                        float l0 = (s0 + cj     <= t0 + r) ? v0 * 0.125f : neg_inf();
                        float l1 = (s0 + cj + 1 <= t0 + r) ? v1 * 0.125f : neg_inf();
                        *reinterpret_cast<float2*>(&smS[r * SSTR + colbase + cj]) = make_float2(l0, l1);
                    }
                    float p0, p1;
                    if (st == qt) {
                        p0 = (cj     <= r) ? v0 * expf(Dq[r] - Ds[cj] + Ls[cj]) : 0.f;
                        p1 = (cj + 1 <= r) ? v1 * expf(Dq[r] - Ds[cj + 1] + Ls[cj + 1]) : 0.f;
                    } else {
                        float re = rowE[r];
                        p0 = v0 * (re * colE[cj]);
                        p1 = v1 * (re * colE[cj + 1]);
                    }
                    float h0 = __bfloat162float(__float2bfloat16_rn(p0));
                    float h1 = __bfloat162float(__float2bfloat16_rn(p1));
                    uint32_t phys = (uint32_t)r * 128u + (uint32_t)((((cj >> 3)) ^ (r & 7)) * 16) + (uint32_t)((cj & 7) * 2);
                    sts4(sb + OFF_K + phys, pack2bf(h0, h1));
                    sts4(sb + OFF_K + 8192u + phys, pack2bf(p0 - h0, p1 - h1));
                }
            }
        }
        __syncthreads();

        {
            int arow = wm * 16 + (lane & 15);
            int asel = lane >> 4;
#pragma unroll
            for (int ks = 0; ks < 4; ks++) {
                uint32_t ph[4], pl[4];
                uint32_t abase = sb + OFF_K + (uint32_t)arow * 128u;
                ldsm4(ph, abase + (uint32_t)(((2 * ks + asel) ^ (arow & 7)) * 16));
                ldsm4(pl, abase + 8192u + (uint32_t)(((2 * ks + asel) ^ (arow & 7)) * 16));
                int vrow = ks * 16 + (lane & 15);
                uint32_t vb = sb + OFF_V + (uint32_t)vrow * 128u;
                uint32_t vh[2][4], vl[2][4];
#pragma unroll
                for (int g = 0; g < 2; g++) {
                    int cch = wn * 4 + 2 * g + (lane >> 4);
                    ldsm4t(vh[g], vb + (uint32_t)((cch ^ (vrow & 7)) * 16));
                    ldsm4t(vl[g], vb + 8192u + (uint32_t)((cch ^ (vrow & 7)) * 16));
                }
#pragma unroll
                for (int j = 0; j < 4; j++) {
                    const uint32_t* b2h = &vh[j >> 1][2 * (j & 1)];
                    const uint32_t* b2l = &vl[j >> 1][2 * (j & 1)];
                    mma_bf16(oacc[j], ph, b2h);
                    mma_bf16(oacc[j], ph, b2l);
                    mma_bf16(oacc[j], pl, b2h);
                }
            }
        }
    }

    // ================= local window path =================
    __syncthreads();
    {
        int r = tid >> 2, g = tid & 3;
        float m = neg_inf();
        for (int c = g; c < nk; c += 4) m = fmaxf(m, smS[r * SSTR + c]);
        m = fmaxf(m, __shfl_xor_sync(0xffffffff, m, 1));
        m = fmaxf(m, __shfl_xor_sync(0xffffffff, m, 2));
        float sum = 0.f;
        for (int c = g; c < nk; c += 4) {
            float e = expf(smS[r * SSTR + c] - m);
            smS[r * SSTR + c] = e;
            sum += e;
        }
        sum += __shfl_xor_sync(0xffffffff, sum, 1);
        sum += __shfl_xor_sync(0xffffffff, sum, 2);
        float inv = 1.f / sum;
        for (int c = g; c < nk; c += 4) smS[r * SSTR + c] *= inv;
    }
    __syncthreads();

    for (int kh = 0; kh < (nk >> 6); kh++) {
        load_split_tile(P + (size_t)(w0 + kh * 64) * PSTR + VOFF + kvh * DHD, sb + OFF_V, sb + OFF_V + 8192u, tid);
#pragma unroll
        for (int i = 0; i < 8; i++) {
            int idx = tid + i * 256;
            int r = idx >> 5, c2 = idx & 31;
            float2 v = *reinterpret_cast<const float2*>(&smS[r * SSTR + kh * 64 + 2 * c2]);
            float h0 = __bfloat162float(__float2bfloat16_rn(v.x));
            float h1 = __bfloat162float(__float2bfloat16_rn(v.y));
            uint32_t phys = (uint32_t)r * 128u + (uint32_t)((((c2 >> 2)) ^ (r & 7)) * 16) + (uint32_t)((c2 & 3) * 4);
            sts4(sb + OFF_K + phys, pack2bf(h0, h1));
            sts4(sb + OFF_K + 8192u + phys, pack2bf(v.x - h0, v.y - h1));
        }
        __syncthreads();
        {
            int arow = wm * 16 + (lane & 15);
            int asel = lane >> 4;
#pragma unroll
            for (int ks = 0; ks < 4; ks++) {
                uint32_t ph[4], pl[4];
                uint32_t abase = sb + OFF_K + (uint32_t)arow * 128u;
                ldsm4(ph, abase + (uint32_t)(((2 * ks + asel) ^ (arow & 7)) * 16));
                ldsm4(pl, abase + 8192u + (uint32_t)(((2 * ks + asel) ^ (arow & 7)) * 16));
                int vrow = ks * 16 + (lane & 15);
                uint32_t vb = sb + OFF_V + (uint32_t)vrow * 128u;
                uint32_t vh[2][4], vl[2][4];
#pragma unroll
                for (int g = 0; g < 2; g++) {
                    int cch = wn * 4 + 2 * g + (lane >> 4);
                    ldsm4t(vh[g], vb + (uint32_t)((cch ^ (vrow & 7)) * 16));
                    ldsm4t(vl[g], vb + 8192u + (uint32_t)((cch ^ (vrow & 7)) * 16));
                }
#pragma unroll
                for (int j = 0; j < 4; j++) {
                    const uint32_t* b2h = &vh[j >> 1][2 * (j & 1)];
                    const uint32_t* b2l = &vl[j >> 1][2 * (j & 1)];
                    mma_bf16(oacc[j], ph, b2h);
                    mma_bf16(oacc[j], ph, b2l);
                    mma_bf16(oacc[j], pl, b2h);
                }
            }
        }
        __syncthreads();
    }

#pragma unroll
    for (int j = 0; j < 4; j++) {
        int col = h * DHD + fcb + 8 * j;
        *reinterpret_cast<float2*>(Y + (size_t)(t0 + fr0) * C_DIM + col) = make_float2(oacc[j][0], oacc[j][1]);
        *reinterpret_cast<float2*>(Y + (size_t)(t0 + fr0 + 8) * C_DIM + col) = make_float2(oacc[j][2], oacc[j][3]);
    }
}

// ---------------- RMSNorm scale (per row) ----------------
__global__ __launch_bounds__(256) void rmsnorm_scale(const float* __restrict__ Y, float* __restrict__ scale)
{
    int t = blockIdx.x, tid = threadIdx.x;
    float4 v = *reinterpret_cast<const float4*>(Y + (size_t)t * C_DIM + tid * 4);
    float ss = v.x * v.x + v.y * v.y + v.z * v.z + v.w * v.w;
#pragma unroll
    for (int off = 16; off; off >>= 1) ss += __shfl_xor_sync(0xffffffff, ss, off);
    __shared__ float red[8];
    if ((tid & 31) == 0) red[tid >> 5] = ss;
    __syncthreads();
    if (tid == 0) {
        float s = 0.f;
#pragma unroll
        for (int i = 0; i < 8; i++) s += red[i];
        scale[t] = rsqrtf(s * (1.f / (float)C_DIM) + 1e-5f);
    }
}

// ---------------- launch ----------------
extern "C" void kernel_launch(void* const* d_in, const int* in_sizes, int n_in,
                              void* d_out, int out_size)
{
    (void)in_sizes; (void)n_in; (void)out_size;
    const float* x    = (const float*)d_in[0];
    const float* Wq   = (const float*)d_in[1];
    const float* Wk   = (const float*)d_in[2];
    const float* Wv   = (const float*)d_in[3];
    const float* Wc   = (const float*)d_in[4];
    const float* Wg   = (const float*)d_in[5];
    const float* bg   = (const float*)d_in[6];
    const float* rmsw = (const float*)d_in[7];
    float* out = (float*)d_out;

    float *P, *D, *L, *Y, *scale;
    __nv_bfloat16 *Wph, *Wpl, *Wch, *Wcl;
    cudaGetSymbolAddress((void**)&P, g_P);
    cudaGetSymbolAddress((void**)&D, g_D);
    cudaGetSymbolAddress((void**)&L, g_L);
    cudaGetSymbolAddress((void**)&Y, g_Y);
    cudaGetSymbolAddress((void**)&scale, g_scale);
    cudaGetSymbolAddress((void**)&Wph, g_Wp_h);
    cudaGetSymbolAddress((void**)&Wpl, g_Wp_l);
    cudaGetSymbolAddress((void**)&Wch, g_Wc_h);
    cudaGetSymbolAddress((void**)&Wcl, g_Wc_l);

    // weight prep: transpose + split (+rmsw fold into Wc), gate weights into pad rows
    transpose_split_all<<<dim3(32, 32, 4), 256>>>(Wq, Wk, Wv, Wc, rmsw, Wph, Wpl, Wch, Wcl);
    gate_wsplit<<<64, 256>>>(Wg, Wph, Wpl);

    // fused Q|K|V|gate projection (RoPE applied in epilogue for Q,K columns)
    size_t smemTC = 65536;
    cudaFuncSetAttribute(gemm_mma, cudaFuncAttributeMaxDynamicSharedMemorySize, (int)smemTC);
    gemm_mma<<<dim3(PSTR / 128, T_SEQ / 128), 256, smemTC>>>(x, Wph, Wpl, P, T_SEQ, PSTR, C_DIM, nullptr, 1);

    scan_kernel<<<NH, 256>>>(P, bg, D, L);

    size_t smemA = OFF_SC + 6 * 64 * sizeof(float);
    cudaFuncSetAttribute(attn_fused, cudaFuncAttributeMaxDynamicSharedMemorySize, (int)smemA);
    attn_fused<<<dim3(T_SEQ / 64, NH), 256, smemA>>>(P, D, L, Y);

    rmsnorm_scale<<<T_SEQ, 256>>>(Y, scale);
    gemm_mma<<<dim3(C_DIM / 128, T_SEQ / 128), 256, smemTC>>>(Y, Wch, Wcl, out, T_SEQ, C_DIM, C_DIM, scale, 0);
}

// round 6
// speedup vs baseline: 2.5059x; 1.0028x over previous
#include <cuda_runtime.h>
#include <cuda_bf16.h>
#include <math.h>
#include <stdint.h>

#define T_SEQ 2048
#define C_DIM 1024
#define NH    16
#define NKV   4
#define DHD   64
#define WINSZ 128
#define PSTR  1664          /* Q(1024) | K(256) | V(256) | gate(16 + 112 pad) */
#define KOFF  1024
#define VOFF  1280
#define GOFF  1536

// ---------------- scratch ----------------
__device__ float g_P[T_SEQ * PSTR];
__device__ float g_D[NH * T_SEQ];
__device__ float g_L[NH * T_SEQ];
__device__ float g_Y[T_SEQ * C_DIM];
__device__ float g_scale[T_SEQ];
__device__ __nv_bfloat16 g_Wp_h[PSTR * C_DIM];
__device__ __nv_bfloat16 g_Wp_l[PSTR * C_DIM];
__device__ __nv_bfloat16 g_Wc_h[C_DIM * C_DIM];
__device__ __nv_bfloat16 g_Wc_l[C_DIM * C_DIM];

__device__ __forceinline__ float neg_inf() { return __int_as_float(0xff800000); }
__device__ __forceinline__ float log_sigmoid_f(float x) {
    return fminf(x, 0.f) - log1pf(expf(-fabsf(x)));
}
__device__ __forceinline__ uint32_t cvta_smem(const void* p) {
    uint32_t a;
    asm("{ .reg .u64 t; cvta.to.shared.u64 t, %1; cvt.u32.u64 %0, t; }" : "=r"(a) : "l"(p));
    return a;
}
__device__ __forceinline__ uint32_t pack2bf(float a, float b) {
    __nv_bfloat162 t = __floats2bfloat162_rn(a, b);
    return *reinterpret_cast<uint32_t*>(&t);
}
__device__ __forceinline__ void ldsm4(uint32_t* r, uint32_t addr) {
    asm volatile("ldmatrix.sync.aligned.m8n8.x4.shared.b16 {%0,%1,%2,%3}, [%4];"
                 : "=r"(r[0]), "=r"(r[1]), "=r"(r[2]), "=r"(r[3]) : "r"(addr));
}
__device__ __forceinline__ void ldsm4t(uint32_t* r, uint32_t addr) {
    asm volatile("ldmatrix.sync.aligned.m8n8.x4.trans.shared.b16 {%0,%1,%2,%3}, [%4];"
                 : "=r"(r[0]), "=r"(r[1]), "=r"(r[2]), "=r"(r[3]) : "r"(addr));
}
__device__ __forceinline__ void mma_bf16(float* c, const uint32_t* a, const uint32_t* b) {
    asm volatile(
        "mma.sync.aligned.m16n8k16.row.col.f32.bf16.bf16.f32 "
        "{%0,%1,%2,%3}, {%4,%5,%6,%7}, {%8,%9}, {%0,%1,%2,%3};"
        : "+f"(c[0]), "+f"(c[1]), "+f"(c[2]), "+f"(c[3])
        : "r"(a[0]), "r"(a[1]), "r"(a[2]), "r"(a[3]), "r"(b[0]), "r"(b[1]));
}
__device__ __forceinline__ void sts16(uint32_t addr, uint32_t a, uint32_t b, uint32_t c, uint32_t d) {
    asm volatile("st.shared.v4.b32 [%0], {%1,%2,%3,%4};" :: "r"(addr), "r"(a), "r"(b), "r"(c), "r"(d) : "memory");
}
__device__ __forceinline__ void sts8(uint32_t addr, uint32_t a, uint32_t b) {
    asm volatile("st.shared.v2.b32 [%0], {%1,%2};" :: "r"(addr), "r"(a), "r"(b) : "memory");
}

// load 64x64 fp32 tile -> split bf16 hi/lo into swizzled smem (128B rows)
__device__ __forceinline__ void load_split_tile(
    const float* __restrict__ gsrc, uint32_t smH, uint32_t smL, int tid)
{
#pragma unroll
    for (int i = 0; i < 4; i++) {
        int f = tid + i * 256;
        int r = f >> 4, q4 = f & 15;
        float4 v = *reinterpret_cast<const float4*>(gsrc + (size_t)r * PSTR + q4 * 4);
        float hx = __bfloat162float(__float2bfloat16_rn(v.x));
        float hy = __bfloat162float(__float2bfloat16_rn(v.y));
        float hz = __bfloat162float(__float2bfloat16_rn(v.z));
        float hw = __bfloat162float(__float2bfloat16_rn(v.w));
        uint32_t phys = (uint32_t)r * 128u + (uint32_t)(((q4 >> 1) ^ (r & 7)) * 16) + (uint32_t)((q4 & 1) * 8);
        sts8(smH + phys, pack2bf(hx, hy), pack2bf(hz, hw));
        sts8(smL + phys, pack2bf(v.x - hx, v.y - hy), pack2bf(v.z - hz, v.w - hw));
    }
}

// ---------------- merged weight transpose + bf16 split ----------------
// z=0..2: Wq/Wk/Wv -> Wp rows; z=3: Wc*rmsw -> Wc; z=4: Wg -> Wp rows GOFF..
__global__ __launch_bounds__(256) void transpose_split_all(
    const float* __restrict__ Wq, const float* __restrict__ Wk,
    const float* __restrict__ Wv, const float* __restrict__ Wc,
    const float* __restrict__ Wg, const float* __restrict__ rmsw,
    __nv_bfloat16* __restrict__ Wph, __nv_bfloat16* __restrict__ Wpl,
    __nv_bfloat16* __restrict__ Wch, __nv_bfloat16* __restrict__ Wcl)
{
    int z = blockIdx.z;
    const float* W; __nv_bfloat16 *Th, *Tl; int N, rowOff = 0; bool useScale = false;
    if (z == 0)      { W = Wq; Th = Wph; Tl = Wpl; N = 1024; }
    else if (z == 1) { W = Wk; Th = Wph; Tl = Wpl; N = 256; rowOff = KOFF; }
    else if (z == 2) { W = Wv; Th = Wph; Tl = Wpl; N = 256; rowOff = VOFF; }
    else if (z == 3) { W = Wc; Th = Wch; Tl = Wcl; N = 1024; useScale = true; }
    else             { W = Wg; Th = Wph; Tl = Wpl; N = 16;  rowOff = GOFF; }
    int n0 = blockIdx.x * 32;
    if (n0 >= N) return;
    int k0 = blockIdx.y * 32;

    __shared__ float s[32][33];
    int tx = threadIdx.x & 31, ty = threadIdx.x >> 5;
#pragma unroll
    for (int i = 0; i < 4; i++) {
        int r = ty + i * 8;
        if (n0 + tx < N) {
            float v = W[(size_t)(k0 + r) * N + n0 + tx];
            if (useScale) v *= rmsw[k0 + r];
            s[r][tx] = v;
        }
    }
    __syncthreads();
#pragma unroll
    for (int i = 0; i < 4; i++) {
        int r = ty + i * 8;
        if (n0 + r < N) {
            float v = s[tx][r];
            __nv_bfloat16 h = __float2bfloat16_rn(v);
            Th[(size_t)(rowOff + n0 + r) * C_DIM + k0 + tx] = h;
            Tl[(size_t)(rowOff + n0 + r) * C_DIM + k0 + tx] = __float2bfloat16_rn(v - __bfloat162float(h));
        }
    }
}

// ---------------- bf16x3 tensor-core GEMM (+row scaling, +RoPE epilogue) ----------------
__global__ __launch_bounds__(256, 1) void gemm_mma(
    const float* __restrict__ A, const __nv_bfloat16* __restrict__ Bh,
    const __nv_bfloat16* __restrict__ Bl, float* __restrict__ C,
    int M, int N, int K, const float* __restrict__ rowScale, int doRope)
{
    extern __shared__ char smc[];
    uint32_t sb = cvta_smem(smc);

    int tid = threadIdx.x, lane = tid & 31, warp = tid >> 5;
    int wm = warp & 3, wn = warp >> 2;
    int m0 = blockIdx.y * 128, n0 = blockIdx.x * 128;

    int row = tid & 127;
    bool isB = tid >= 128;
    const float* ag = A + (size_t)(m0 + row) * K;
    const __nv_bfloat16* bhg = Bh + (size_t)(n0 + row) * K;
    const __nv_bfloat16* blg = Bl + (size_t)(n0 + row) * K;
    float rs = (!isB && rowScale) ? rowScale[m0 + row] : 1.0f;

    float acc[2][8][4] = {};
    float4 pa[8];
    uint4 pbh[4], pbl[4];

    if (!isB) {
#pragma unroll
        for (int i = 0; i < 8; i++) pa[i] = *reinterpret_cast<const float4*>(ag + i * 4);
    } else {
#pragma unroll
        for (int c = 0; c < 4; c++) {
            pbh[c] = *reinterpret_cast<const uint4*>(bhg + c * 8);
            pbl[c] = *reinterpret_cast<const uint4*>(blg + c * 8);
        }
    }

    int nkt = K / 32;
    for (int kt = 0; kt < nkt; ++kt) {
        uint32_t stage = sb + (uint32_t)(kt & 1) * 32768u;
        uint32_t aB = stage, bB = stage + 16384u;

        if (!isB) {
            uint32_t dst = aB + (uint32_t)row * 128u;
            int rsw = row & 7;
#pragma unroll
            for (int c = 0; c < 4; c++) {
                float4 v0 = pa[2 * c], v1 = pa[2 * c + 1];
                v0.x *= rs; v0.y *= rs; v0.z *= rs; v0.w *= rs;
                v1.x *= rs; v1.y *= rs; v1.z *= rs; v1.w *= rs;
                float h0 = __bfloat162float(__float2bfloat16_rn(v0.x));
                float h1 = __bfloat162float(__float2bfloat16_rn(v0.y));
                float h2 = __bfloat162float(__float2bfloat16_rn(v0.z));
                float h3 = __bfloat162float(__float2bfloat16_rn(v0.w));
                float h4 = __bfloat162float(__float2bfloat16_rn(v1.x));
                float h5 = __bfloat162float(__float2bfloat16_rn(v1.y));
                float h6 = __bfloat162float(__float2bfloat16_rn(v1.z));
                float h7 = __bfloat162float(__float2bfloat16_rn(v1.w));
                sts16(dst + (uint32_t)((c ^ rsw) * 16),
                      pack2bf(h0, h1), pack2bf(h2, h3), pack2bf(h4, h5), pack2bf(h6, h7));
                sts16(dst + (uint32_t)(((4 + c) ^ rsw) * 16),
                      pack2bf(v0.x - h0, v0.y - h1), pack2bf(v0.z - h2, v0.w - h3),
                      pack2bf(v1.x - h4, v1.y - h5), pack2bf(v1.z - h6, v1.w - h7));
            }
        } else {
            uint32_t dst = bB + (uint32_t)row * 128u;
            int rsw = row & 7;
#pragma unroll
            for (int c = 0; c < 4; c++) {
                sts16(dst + (uint32_t)((c ^ rsw) * 16), pbh[c].x, pbh[c].y, pbh[c].z, pbh[c].w);
                sts16(dst + (uint32_t)(((4 + c) ^ rsw) * 16), pbl[c].x, pbl[c].y, pbl[c].z, pbl[c].w);
            }
        }
        __syncthreads();

        if (kt + 1 < nkt) {
            int kb = (kt + 1) * 32;
            if (!isB) {
#pragma unroll
                for (int i = 0; i < 8; i++) pa[i] = *reinterpret_cast<const float4*>(ag + kb + i * 4);
            } else {
#pragma unroll
                for (int c = 0; c < 4; c++) {
                    pbh[c] = *reinterpret_cast<const uint4*>(bhg + kb + c * 8);
                    pbl[c] = *reinterpret_cast<const uint4*>(blg + kb + c * 8);
                }
            }
        }

#pragma unroll
        for (int s = 0; s < 2; s++) {
            uint32_t ahi[2][4], alo[2][4];
            int arow = wm * 32 + (lane & 15);
            int asel = lane >> 4;
#pragma unroll
            for (int t = 0; t < 2; t++) {
                int r = arow + t * 16;
                uint32_t base = aB + (uint32_t)r * 128u;
                ldsm4(ahi[t], base + (uint32_t)((((2 * s) + asel) ^ (r & 7)) * 16));
                ldsm4(alo[t], base + (uint32_t)(((4 + 2 * s + asel) ^ (r & 7)) * 16));
            }
            uint32_t bhi[4][4], blo[4][4];
            int nrow = wn * 64 + (lane & 7) + ((lane >> 4) << 3);
            int bsel = (lane >> 3) & 1;
#pragma unroll
            for (int g = 0; g < 4; g++) {
                int r = nrow + g * 16;
                uint32_t base = bB + (uint32_t)r * 128u;
                ldsm4(bhi[g], base + (uint32_t)((((2 * s) + bsel) ^ (r & 7)) * 16));
                ldsm4(blo[g], base + (uint32_t)(((4 + 2 * s + bsel) ^ (r & 7)) * 16));
            }
#pragma unroll
            for (int t = 0; t < 2; t++)
#pragma unroll
                for (int j = 0; j < 8; j++) {
                    const uint32_t* bh2 = &bhi[j >> 1][2 * (j & 1)];
                    const uint32_t* bl2 = &blo[j >> 1][2 * (j & 1)];
                    mma_bf16(acc[t][j], ahi[t], bh2);
                    mma_bf16(acc[t][j], ahi[t], bl2);
                    mma_bf16(acc[t][j], alo[t], bh2);
                }
        }
    }

    if (doRope && (n0 + wn * 64) < 1280) {
#pragma unroll
        for (int j = 0; j < 4; j++) {
#pragma unroll
            for (int e = 0; e < 2; e++) {
                int d = j * 8 + 2 * (lane & 3) + e;
                float invf = expf(-(float)(2 * d) * (9.210340371976184f / 64.f));
#pragma unroll
                for (int mt = 0; mt < 2; mt++) {
#pragma unroll
                    for (int rh = 0; rh < 2; rh++) {
                        int trow = m0 + wm * 32 + mt * 16 + (lane >> 2) + rh * 8;
                        float sn, cs;
                        sincosf((float)trow * invf, &sn, &cs);
                        int k = 2 * rh + e;
                        float a = acc[mt][j][k], b = acc[mt][j + 4][k];
                        acc[mt][j][k]     = a * cs - b * sn;
                        acc[mt][j + 4][k] = b * cs + a * sn;
                    }
                }
            }
        }
    }

#pragma unroll
    for (int t = 0; t < 2; t++) {
        int r0 = m0 + wm * 32 + t * 16 + (lane >> 2);
#pragma unroll
        for (int j = 0; j < 8; j++) {
            int col = n0 + wn * 64 + j * 8 + 2 * (lane & 3);
            *reinterpret_cast<float2*>(C + (size_t)r0 * N + col) = make_float2(acc[t][j][0], acc[t][j][1]);
            *reinterpret_cast<float2*>(C + (size_t)(r0 + 8) * N + col) = make_float2(acc[t][j][2], acc[t][j][3]);
        }
    }
}

// ---------------- per-head scan (warp-shuffle) ----------------
__global__ __launch_bounds__(256) void scan_kernel(
    const float* __restrict__ P, const float* __restrict__ bg,
    float* __restrict__ D, float* __restrict__ L)
{
    int h = blockIdx.x, tid = threadIdx.x, lane = tid & 31, wid = tid >> 5;
    float b = bg[h];
    float vals[8];
    float run = 0.f;
#pragma unroll
    for (int i = 0; i < 8; i++) {
        int t = tid * 8 + i;
        float gg = P[(size_t)t * PSTR + GOFF + h] + b;
        run += log_sigmoid_f(gg);
        vals[i] = run;
        L[h * T_SEQ + t] = log_sigmoid_f(-gg);
    }
    float x = run;
#pragma unroll
    for (int off = 1; off < 32; off <<= 1) {
        float y = __shfl_up_sync(0xffffffff, x, off);
        if (lane >= off) x += y;
    }
    __shared__ float wsum[8];
    if (lane == 31) wsum[wid] = x;
    __syncthreads();
    float woff = 0.f;
#pragma unroll
    for (int w = 0; w < 8; w++) if (w < wid) woff += wsum[w];
    float excl = x - run + woff;
#pragma unroll
    for (int i = 0; i < 8; i++) D[h * T_SEQ + tid * 8 + i] = vals[i] + excl;
}

// ---------------- fused attention (register-P FA2 style) ----------------
#define OFF_Q  0u
#define OFF_K  16384u
#define OFF_V  32768u
#define OFF_S  49152u
#define SSTR   132
#define OFF_SC (49152u + 64u * SSTR * 4u)

// per-warp PV: O[j] += P(kslice of this wn) @ V; V^T fragments via ldsm4t
__device__ __forceinline__ void pv_mma(
    uint32_t sbV, uint32_t pah[2][4], uint32_t pal[2][4],
    float (*oacc)[4], int wn, int lane)
{
#pragma unroll
    for (int u = 0; u < 2; u++) {
        int vrow = wn * 32 + u * 16 + (lane & 15);
        uint32_t vb = sbV + (uint32_t)vrow * 128u;
#pragma unroll
        for (int gg = 0; gg < 4; gg++) {
            int cch = 2 * gg + (lane >> 4);
            uint32_t vh[4], vl[4];
            ldsm4t(vh, vb + (uint32_t)((cch ^ (vrow & 7)) * 16));
            ldsm4t(vl, vb + 8192u + (uint32_t)((cch ^ (vrow & 7)) * 16));
#pragma unroll
            for (int jj = 0; jj < 2; jj++) {
                int j = gg * 2 + jj;
                mma_bf16(oacc[j], pah[u], &vh[2 * jj]);
                mma_bf16(oacc[j], pah[u], &vl[2 * jj]);
                mma_bf16(oacc[j], pal[u], &vh[2 * jj]);
            }
        }
    }
}

__global__ __launch_bounds__(256, 2) void attn_fused(
    const float* __restrict__ P, const float* __restrict__ D,
    const float* __restrict__ L, float* __restrict__ Y)
{
    extern __shared__ char smc[];
    uint32_t sb = cvta_smem(smc);
    float* smS  = reinterpret_cast<float*>(smc + OFF_S);
    float* Dq   = reinterpret_cast<float*>(smc + OFF_SC);
    float* rowE = Dq + 64;
    float* Ds   = rowE + 64;
    float* Ls   = Ds + 64;
    float* colE = Ls + 64;

    int qt = blockIdx.x, h = blockIdx.y;
    int kvh = h >> 2;
    int tid = threadIdx.x, lane = tid & 31, warp = tid >> 5;
    int wm = warp & 3, wn = warp >> 2;
    int t0 = qt * 64;
    int w0 = (t0 / WINSZ) * WINSZ;
    int wt0 = w0 / 64;
    int nk = t0 - w0 + 64;

    load_split_tile(P + (size_t)t0 * PSTR + h * DHD, sb + OFF_Q, sb + OFF_Q + 8192u, tid);
    if (tid < 64) Dq[tid] = D[h * T_SEQ + t0 + tid];
    __syncthreads();
    float dq0 = Dq[0];
    if (tid < 64) rowE[tid] = expf(Dq[tid] - dq0);

    int fr0 = wm * 16 + (lane >> 2);
    int fcb = wn * 32 + 2 * (lane & 3);

    float oacc[8][4] = {};

    for (int st = qt; st >= 0; --st) {
        int s0 = st * 64;
        bool inwin = (st >= wt0);
        if (!inwin) {
            float dend = D[h * T_SEQ + s0 + 63];
            if (dq0 - dend < -88.f) break;
        }
        __syncthreads();   // prior K/V reads complete

        load_split_tile(P + (size_t)s0 * PSTR + KOFF + kvh * DHD, sb + OFF_K, sb + OFF_K + 8192u, tid);
        load_split_tile(P + (size_t)s0 * PSTR + VOFF + kvh * DHD, sb + OFF_V, sb + OFF_V + 8192u, tid);
        if (tid < 64) {
            float ds = D[h * T_SEQ + s0 + tid];
            float ls = L[h * T_SEQ + s0 + tid];
            Ds[tid] = ds; Ls[tid] = ls;
            colE[tid] = expf(dq0 - ds + ls);
        }
        __syncthreads();

        // ---- S = Q @ K^T ----
        float sacc[4][4] = {};
        {
            int arow = wm * 16 + (lane & 15);
            int asel = lane >> 4;
            int nrow = wn * 32 + (lane & 7) + ((lane >> 4) << 3);
            int bsel = (lane >> 3) & 1;
#pragma unroll
            for (int ks = 0; ks < 4; ks++) {
                uint32_t ah[4], al[4];
                uint32_t abase = sb + OFF_Q + (uint32_t)arow * 128u;
                ldsm4(ah, abase + (uint32_t)(((2 * ks + asel) ^ (arow & 7)) * 16));
                ldsm4(al, abase + 8192u + (uint32_t)(((2 * ks + asel) ^ (arow & 7)) * 16));
                uint32_t bh[2][4], bl[2][4];
#pragma unroll
                for (int g = 0; g < 2; g++) {
                    int r = nrow + g * 16;
                    uint32_t bbase = sb + OFF_K + (uint32_t)r * 128u;
                    ldsm4(bh[g], bbase + (uint32_t)(((2 * ks + bsel) ^ (r & 7)) * 16));
                    ldsm4(bl[g], bbase + 8192u + (uint32_t)(((2 * ks + bsel) ^ (r & 7)) * 16));
                }
#pragma unroll
                for (int j = 0; j < 4; j++) {
                    const uint32_t* b2h = &bh[j >> 1][2 * (j & 1)];
                    const uint32_t* b2l = &bl[j >> 1][2 * (j & 1)];
                    mma_bf16(sacc[j], ah, b2h);
                    mma_bf16(sacc[j], ah, b2l);
                    mma_bf16(sacc[j], al, b2h);
                }
            }
        }

        // ---- weight in registers, stash local scores, build P A-fragments ----
        uint32_t pah[2][4], pal[2][4];
        {
            int colbase = s0 - w0;
#pragma unroll
            for (int j = 0; j < 4; j++) {
                int cj = fcb + 8 * j;
#pragma unroll
                for (int half = 0; half < 2; half++) {
                    int r = fr0 + half * 8;
                    float v0 = sacc[j][2 * half], v1 = sacc[j][2 * half + 1];
                    if (inwin) {
                        float l0 = (s0 + cj     <= t0 + r) ? v0 * 0.125f : neg_inf();
                        float l1 = (s0 + cj + 1 <= t0 + r) ? v1 * 0.125f : neg_inf();
                        *reinterpret_cast<float2*>(&smS[r * SSTR + colbase + cj]) = make_float2(l0, l1);
                    }
                    float p0, p1;
                    if (st == qt) {
                        p0 = (cj     <= r) ? v0 * expf(Dq[r] - Ds[cj] + Ls[cj]) : 0.f;
                        p1 = (cj + 1 <= r) ? v1 * expf(Dq[r] - Ds[cj + 1] + Ls[cj + 1]) : 0.f;
                    } else {
                        float re = rowE[r];
                        p0 = v0 * (re * colE[cj]);
                        p1 = v1 * (re * colE[cj + 1]);
                    }
                    float h0 = __bfloat162float(__float2bfloat16_rn(p0));
                    float h1 = __bfloat162float(__float2bfloat16_rn(p1));
                    int u = j >> 1, ri = (j & 1) * 2 + half;
                    pah[u][ri] = pack2bf(h0, h1);
                    pal[u][ri] = pack2bf(p0 - h0, p1 - h1);
                }
            }
        }

        // ---- O += P @ V directly from registers ----
        pv_mma(sb + OFF_V, pah, pal, oacc, wn, lane);
    }

    // ================= local window path =================
    __syncthreads();
    {
        int r = tid >> 2, g = tid & 3;
        float m = neg_inf();
        for (int c = g; c < nk; c += 4) m = fmaxf(m, smS[r * SSTR + c]);
        m = fmaxf(m, __shfl_xor_sync(0xffffffff, m, 1));
        m = fmaxf(m, __shfl_xor_sync(0xffffffff, m, 2));
        float sum = 0.f;
        for (int c = g; c < nk; c += 4) {
            float e = expf(smS[r * SSTR + c] - m);
            smS[r * SSTR + c] = e;
            sum += e;
        }
        sum += __shfl_xor_sync(0xffffffff, sum, 1);
        sum += __shfl_xor_sync(0xffffffff, sum, 2);
        float inv = 1.f / sum;
        for (int c = g; c < nk; c += 4) smS[r * SSTR + c] *= inv;
    }

    for (int kh = 0; kh < (nk >> 6); kh++) {
        __syncthreads();   // prior V reads complete (and softmax visible on first pass)
        load_split_tile(P + (size_t)(w0 + kh * 64) * PSTR + VOFF + kvh * DHD, sb + OFF_V, sb + OFF_V + 8192u, tid);
        __syncthreads();
        uint32_t pah[2][4], pal[2][4];
#pragma unroll
        for (int u = 0; u < 2; u++) {
            int bc = kh * 64 + wn * 32 + u * 16 + 2 * (lane & 3);
            float2 f0 = *reinterpret_cast<const float2*>(&smS[fr0 * SSTR + bc]);
            float2 f1 = *reinterpret_cast<const float2*>(&smS[(fr0 + 8) * SSTR + bc]);
            float2 f2 = *reinterpret_cast<const float2*>(&smS[fr0 * SSTR + bc + 8]);
            float2 f3 = *reinterpret_cast<const float2*>(&smS[(fr0 + 8) * SSTR + bc + 8]);
            float h;
            h = __bfloat162float(__float2bfloat16_rn(f0.x));
            float h2 = __bfloat162float(__float2bfloat16_rn(f0.y));
            pah[u][0] = pack2bf(h, h2); pal[u][0] = pack2bf(f0.x - h, f0.y - h2);
            h = __bfloat162float(__float2bfloat16_rn(f1.x));
            h2 = __bfloat162float(__float2bfloat16_rn(f1.y));
            pah[u][1] = pack2bf(h, h2); pal[u][1] = pack2bf(f1.x - h, f1.y - h2);
            h = __bfloat162float(__float2bfloat16_rn(f2.x));
            h2 = __bfloat162float(__float2bfloat16_rn(f2.y));
            pah[u][2] = pack2bf(h, h2); pal[u][2] = pack2bf(f2.x - h, f2.y - h2);
            h = __bfloat162float(__float2bfloat16_rn(f3.x));
            h2 = __bfloat162float(__float2bfloat16_rn(f3.y));
            pah[u][3] = pack2bf(h, h2); pal[u][3] = pack2bf(f3.x - h, f3.y - h2);
        }
        pv_mma(sb + OFF_V, pah, pal, oacc, wn, lane);
    }

    // ---- cross-warp (wn pair) reduction, write Y ----
    __syncthreads();
    float* redb = reinterpret_cast<float*>(smc + OFF_K);
    if (wn == 1) {
        int base = (wm * 32 + lane) * 32;
#pragma unroll
        for (int j = 0; j < 8; j++)
#pragma unroll
            for (int k = 0; k < 4; k++) redb[base + j * 4 + k] = oacc[j][k];
    }
    __syncthreads();
    if (wn == 0) {
        int base = (wm * 32 + lane) * 32;
#pragma unroll
        for (int j = 0; j < 8; j++) {
            float o0 = oacc[j][0] + redb[base + j * 4 + 0];
            float o1 = oacc[j][1] + redb[base + j * 4 + 1];
            float o2 = oacc[j][2] + redb[base + j * 4 + 2];
            float o3 = oacc[j][3] + redb[base + j * 4 + 3];
            int col = h * DHD + j * 8 + 2 * (lane & 3);
            *reinterpret_cast<float2*>(Y + (size_t)(t0 + fr0) * C_DIM + col) = make_float2(o0, o1);
            *reinterpret_cast<float2*>(Y + (size_t)(t0 + fr0 + 8) * C_DIM + col) = make_float2(o2, o3);
        }
    }
}

// ---------------- RMSNorm scale ----------------
__global__ __launch_bounds__(256) void rmsnorm_scale(const float* __restrict__ Y, float* __restrict__ scale)
{
    int t = blockIdx.x, tid = threadIdx.x;
    float4 v = *reinterpret_cast<const float4*>(Y + (size_t)t * C_DIM + tid * 4);
    float ss = v.x * v.x + v.y * v.y + v.z * v.z + v.w * v.w;
#pragma unroll
    for (int off = 16; off; off >>= 1) ss += __shfl_xor_sync(0xffffffff, ss, off);
    __shared__ float red[8];
    if ((tid & 31) == 0) red[tid >> 5] = ss;
    __syncthreads();
    if (tid == 0) {
        float s = 0.f;
#pragma unroll
        for (int i = 0; i < 8; i++) s += red[i];
        scale[t] = rsqrtf(s * (1.f / (float)C_DIM) + 1e-5f);
    }
}

// ---------------- launch ----------------
extern "C" void kernel_launch(void* const* d_in, const int* in_sizes, int n_in,
                              void* d_out, int out_size)
{
    (void)in_sizes; (void)n_in; (void)out_size;
    const float* x    = (const float*)d_in[0];
    const float* Wq   = (const float*)d_in[1];
    const float* Wk   = (const float*)d_in[2];
    const float* Wv   = (const float*)d_in[3];
    const float* Wc   = (const float*)d_in[4];
    const float* Wg   = (const float*)d_in[5];
    const float* bg   = (const float*)d_in[6];
    const float* rmsw = (const float*)d_in[7];
    float* out = (float*)d_out;

    float *P, *D, *L, *Y, *scale;
    __nv_bfloat16 *Wph, *Wpl, *Wch, *Wcl;
    cudaGetSymbolAddress((void**)&P, g_P);
    cudaGetSymbolAddress((void**)&D, g_D);
    cudaGetSymbolAddress((void**)&L, g_L);
    cudaGetSymbolAddress((void**)&Y, g_Y);
    cudaGetSymbolAddress((void**)&scale, g_scale);
    cudaGetSymbolAddress((void**)&Wph, g_Wp_h);
    cudaGetSymbolAddress((void**)&Wpl, g_Wp_l);
    cudaGetSymbolAddress((void**)&Wch, g_Wc_h);
    cudaGetSymbolAddress((void**)&Wcl, g_Wc_l);

    transpose_split_all<<<dim3(32, 32, 5), 256>>>(Wq, Wk, Wv, Wc, Wg, rmsw, Wph, Wpl, Wch, Wcl);

    size_t smemTC = 65536;
    cudaFuncSetAttribute(gemm_mma, cudaFuncAttributeMaxDynamicSharedMemorySize, (int)smemTC);
    gemm_mma<<<dim3(PSTR / 128, T_SEQ / 128), 256, smemTC>>>(x, Wph, Wpl, P, T_SEQ, PSTR, C_DIM, nullptr, 1);

    scan_kernel<<<NH, 256>>>(P, bg, D, L);

    size_t smemA = OFF_SC + 6 * 64 * sizeof(float);
    cudaFuncSetAttribute(attn_fused, cudaFuncAttributeMaxDynamicSharedMemorySize, (int)smemA);
    attn_fused<<<dim3(T_SEQ / 64, NH), 256, smemA>>>(P, D, L, Y);

    rmsnorm_scale<<<T_SEQ, 256>>>(Y, scale);
    gemm_mma<<<dim3(C_DIM / 128, T_SEQ / 128), 256, smemTC>>>(Y, Wch, Wcl, out, T_SEQ, C_DIM, C_DIM, scale, 0);
}

// round 7
// speedup vs baseline: 3.3871x; 1.3516x over previous
#include <cuda_runtime.h>
#include <cuda_bf16.h>
#include <math.h>
#include <stdint.h>

#define T_SEQ 2048
#define C_DIM 1024
#define NH    16
#define NKV   4
#define DHD   64
#define WINSZ 128
#define PSTR  1664          /* Q(1024) | K(256) | V(256) | gate(16 + 112 pad) */
#define KOFF  1024
#define VOFF  1280
#define GOFF  1536

// ---------------- scratch ----------------
__device__ float g_P[T_SEQ * PSTR];
__device__ float g_D[NH * T_SEQ];
__device__ float g_L[NH * T_SEQ];
__device__ float g_Y[T_SEQ * C_DIM];
__device__ __nv_bfloat16 g_Xh[T_SEQ * C_DIM];
__device__ __nv_bfloat16 g_Xl[T_SEQ * C_DIM];
__device__ __nv_bfloat16 g_Yh[T_SEQ * C_DIM];
__device__ __nv_bfloat16 g_Yl[T_SEQ * C_DIM];
__device__ __nv_bfloat16 g_Wp_h[PSTR * C_DIM];
__device__ __nv_bfloat16 g_Wp_l[PSTR * C_DIM];
__device__ __nv_bfloat16 g_Wc_h[C_DIM * C_DIM];
__device__ __nv_bfloat16 g_Wc_l[C_DIM * C_DIM];

__device__ __forceinline__ float neg_inf() { return __int_as_float(0xff800000); }
__device__ __forceinline__ float log_sigmoid_f(float x) {
    return fminf(x, 0.f) - log1pf(expf(-fabsf(x)));
}
__device__ __forceinline__ uint32_t cvta_smem(const void* p) {
    uint32_t a;
    asm("{ .reg .u64 t; cvta.to.shared.u64 t, %1; cvt.u32.u64 %0, t; }" : "=r"(a) : "l"(p));
    return a;
}
__device__ __forceinline__ uint32_t pack2bf(float a, float b) {
    __nv_bfloat162 t = __floats2bfloat162_rn(a, b);
    return *reinterpret_cast<uint32_t*>(&t);
}
__device__ __forceinline__ void ldsm4(uint32_t* r, uint32_t addr) {
    asm volatile("ldmatrix.sync.aligned.m8n8.x4.shared.b16 {%0,%1,%2,%3}, [%4];"
                 : "=r"(r[0]), "=r"(r[1]), "=r"(r[2]), "=r"(r[3]) : "r"(addr));
}
__device__ __forceinline__ void ldsm4t(uint32_t* r, uint32_t addr) {
    asm volatile("ldmatrix.sync.aligned.m8n8.x4.trans.shared.b16 {%0,%1,%2,%3}, [%4];"
                 : "=r"(r[0]), "=r"(r[1]), "=r"(r[2]), "=r"(r[3]) : "r"(addr));
}
__device__ __forceinline__ void mma_bf16(float* c, const uint32_t* a, const uint32_t* b) {
    asm volatile(
        "mma.sync.aligned.m16n8k16.row.col.f32.bf16.bf16.f32 "
        "{%0,%1,%2,%3}, {%4,%5,%6,%7}, {%8,%9}, {%0,%1,%2,%3};"
        : "+f"(c[0]), "+f"(c[1]), "+f"(c[2]), "+f"(c[3])
        : "r"(a[0]), "r"(a[1]), "r"(a[2]), "r"(a[3]), "r"(b[0]), "r"(b[1]));
}
__device__ __forceinline__ void sts8(uint32_t addr, uint32_t a, uint32_t b) {
    asm volatile("st.shared.v2.b32 [%0], {%1,%2};" :: "r"(addr), "r"(a), "r"(b) : "memory");
}
__device__ __forceinline__ void cpasync16(uint32_t dst, const void* src) {
    asm volatile("cp.async.cg.shared.global [%0], [%1], 16;" :: "r"(dst), "l"(src) : "memory");
}
#define CP_COMMIT() asm volatile("cp.async.commit_group;" ::: "memory")
#define CP_WAIT(n)  asm volatile("cp.async.wait_group %0;" :: "n"(n) : "memory")

// swizzled offset within a 128x16 bf16 tile (4KB): row in [0,128), c in {0,1} (16B chunks)
__device__ __forceinline__ uint32_t phys16(int row, int c) {
    return (uint32_t)((row >> 2) * 128 + (((((row & 3) * 2) + c) ^ ((row >> 2) & 1)) * 16));
}

// load 64x64 fp32 tile -> split bf16 hi/lo into swizzled smem (128B rows) [attn kernel]
__device__ __forceinline__ void load_split_tile(
    const float* __restrict__ gsrc, uint32_t smH, uint32_t smL, int tid)
{
#pragma unroll
    for (int i = 0; i < 4; i++) {
        int f = tid + i * 256;
        int r = f >> 4, q4 = f & 15;
        float4 v = *reinterpret_cast<const float4*>(gsrc + (size_t)r * PSTR + q4 * 4);
        float hx = __bfloat162float(__float2bfloat16_rn(v.x));
        float hy = __bfloat162float(__float2bfloat16_rn(v.y));
        float hz = __bfloat162float(__float2bfloat16_rn(v.z));
        float hw = __bfloat162float(__float2bfloat16_rn(v.w));
        uint32_t phys = (uint32_t)r * 128u + (uint32_t)(((q4 >> 1) ^ (r & 7)) * 16) + (uint32_t)((q4 & 1) * 8);
        sts8(smH + phys, pack2bf(hx, hy), pack2bf(hz, hw));
        sts8(smL + phys, pack2bf(v.x - hx, v.y - hy), pack2bf(v.z - hz, v.w - hw));
    }
}

// ---------------- merged weight transpose + bf16 split ----------------
__global__ __launch_bounds__(256) void transpose_split_all(
    const float* __restrict__ Wq, const float* __restrict__ Wk,
    const float* __restrict__ Wv, const float* __restrict__ Wc,
    const float* __restrict__ Wg, const float* __restrict__ rmsw,
    __nv_bfloat16* __restrict__ Wph, __nv_bfloat16* __restrict__ Wpl,
    __nv_bfloat16* __restrict__ Wch, __nv_bfloat16* __restrict__ Wcl)
{
    int z = blockIdx.z;
    const float* W; __nv_bfloat16 *Th, *Tl; int N, rowOff = 0; bool useScale = false;
    if (z == 0)      { W = Wq; Th = Wph; Tl = Wpl; N = 1024; }
    else if (z == 1) { W = Wk; Th = Wph; Tl = Wpl; N = 256; rowOff = KOFF; }
    else if (z == 2) { W = Wv; Th = Wph; Tl = Wpl; N = 256; rowOff = VOFF; }
    else if (z == 3) { W = Wc; Th = Wch; Tl = Wcl; N = 1024; useScale = true; }
    else             { W = Wg; Th = Wph; Tl = Wpl; N = 16;  rowOff = GOFF; }
    int n0 = blockIdx.x * 32;
    if (n0 >= N) return;
    int k0 = blockIdx.y * 32;

    __shared__ float s[32][33];
    int tx = threadIdx.x & 31, ty = threadIdx.x >> 5;
#pragma unroll
    for (int i = 0; i < 4; i++) {
        int r = ty + i * 8;
        if (n0 + tx < N) {
            float v = W[(size_t)(k0 + r) * N + n0 + tx];
            if (useScale) v *= rmsw[k0 + r];
            s[r][tx] = v;
        }
    }
    __syncthreads();
#pragma unroll
    for (int i = 0; i < 4; i++) {
        int r = ty + i * 8;
        if (n0 + r < N) {
            float v = s[tx][r];
            __nv_bfloat16 h = __float2bfloat16_rn(v);
            Th[(size_t)(rowOff + n0 + r) * C_DIM + k0 + tx] = h;
            Tl[(size_t)(rowOff + n0 + r) * C_DIM + k0 + tx] = __float2bfloat16_rn(v - __bfloat162float(h));
        }
    }
}

// ---------------- activation split (optional fused RMSNorm row scale) ----------------
// one block per row of C_DIM floats
__global__ __launch_bounds__(256) void split_act(
    const float* __restrict__ X, __nv_bfloat16* __restrict__ Ah,
    __nv_bfloat16* __restrict__ Al, int doNorm)
{
    int t = blockIdx.x, tid = threadIdx.x;
    float4 v = *reinterpret_cast<const float4*>(X + (size_t)t * C_DIM + tid * 4);
    float scale = 1.0f;
    if (doNorm) {
        float ss = v.x * v.x + v.y * v.y + v.z * v.z + v.w * v.w;
#pragma unroll
        for (int off = 16; off; off >>= 1) ss += __shfl_xor_sync(0xffffffff, ss, off);
        __shared__ float red[8];
        if ((tid & 31) == 0) red[tid >> 5] = ss;
        __syncthreads();
        float s = red[0];
#pragma unroll
        for (int i = 1; i < 8; i++) s += red[i];
        scale = rsqrtf(s * (1.f / (float)C_DIM) + 1e-5f);
    }
    v.x *= scale; v.y *= scale; v.z *= scale; v.w *= scale;
    float h0 = __bfloat162float(__float2bfloat16_rn(v.x));
    float h1 = __bfloat162float(__float2bfloat16_rn(v.y));
    float h2 = __bfloat162float(__float2bfloat16_rn(v.z));
    float h3 = __bfloat162float(__float2bfloat16_rn(v.w));
    uint2 hh = make_uint2(pack2bf(h0, h1), pack2bf(h2, h3));
    uint2 ll = make_uint2(pack2bf(v.x - h0, v.y - h1), pack2bf(v.z - h2, v.w - h3));
    *reinterpret_cast<uint2*>(Ah + (size_t)t * C_DIM + tid * 4) = hh;
    *reinterpret_cast<uint2*>(Al + (size_t)t * C_DIM + tid * 4) = ll;
}

// ---------------- bf16x3 GEMM, both operands pre-split, cp.async 3-stage pipeline ----------------
// C[M][N] = (Ah+Al)[M][K] @ (Bh+Bl)[N][K]^T   (dropping Al*Bl)
// 128x128 CTA tile, k-tile 16, 256 threads, 8 warps (4m x 2n).
__global__ __launch_bounds__(256, 2) void gemm_bf16(
    const __nv_bfloat16* __restrict__ Ah, const __nv_bfloat16* __restrict__ Al,
    const __nv_bfloat16* __restrict__ Bh, const __nv_bfloat16* __restrict__ Bl,
    float* __restrict__ C, int M, int N, int K, int doRope)
{
    extern __shared__ char smc[];
    uint32_t sb = cvta_smem(smc);   // 3 stages x 16KB; stage: Ah|Al|Bh|Bl 4KB each

    int tid = threadIdx.x, lane = tid & 31, warp = tid >> 5;
    int wm = warp & 3, wn = warp >> 2;
    int m0 = blockIdx.y * 128, n0 = blockIdx.x * 128;

    int lrow = tid >> 1, lc = tid & 1;            // cp.async mapping
    uint32_t ldst = phys16(lrow, lc);
    const __nv_bfloat16* gA_h = Ah + (size_t)(m0 + lrow) * K + lc * 8;
    const __nv_bfloat16* gA_l = Al + (size_t)(m0 + lrow) * K + lc * 8;
    const __nv_bfloat16* gB_h = Bh + (size_t)(n0 + lrow) * K + lc * 8;
    const __nv_bfloat16* gB_l = Bl + (size_t)(n0 + lrow) * K + lc * 8;

    int nkt = K / 16;
    float acc[2][8][4] = {};

    // prologue: stages 0,1
#pragma unroll
    for (int p = 0; p < 2; p++) {
        uint32_t st = sb + (uint32_t)p * 16384u;
        cpasync16(st + ldst,          gA_h + p * 16);
        cpasync16(st + 4096u + ldst,  gA_l + p * 16);
        cpasync16(st + 8192u + ldst,  gB_h + p * 16);
        cpasync16(st + 12288u + ldst, gB_l + p * 16);
        CP_COMMIT();
    }

    // fragment addressing (within 4KB tile)
    int aRow = (lane & 15), aC = lane >> 4;              // + wm*32 + t*16
    int bRowBase = (lane & 7) + ((lane >> 4) << 3);      // + g*16
    int bC = (lane >> 3) & 1;

    for (int kt = 0; kt < nkt; ++kt) {
        if (kt + 2 < nkt) { CP_WAIT(1); } else { CP_WAIT(0); }
        __syncthreads();

        uint32_t st = sb + (uint32_t)(kt % 3) * 16384u;
        uint32_t ah[2][4], al[2][4];
#pragma unroll
        for (int t = 0; t < 2; t++) {
            int r = wm * 32 + t * 16 + aRow;
            ldsm4(ah[t], st + phys16(r, aC));
            ldsm4(al[t], st + 4096u + phys16(r, aC));
        }
#pragma unroll
        for (int g = 0; g < 4; g++) {
            int r = wn * 64 + g * 16 + bRowBase;
            uint32_t bh[4], bl[4];
            ldsm4(bh, st + 8192u + phys16(r, bC));
            ldsm4(bl, st + 12288u + phys16(r, bC));
#pragma unroll
            for (int t = 0; t < 2; t++)
#pragma unroll
                for (int jj = 0; jj < 2; jj++) {
                    int j = g * 2 + jj;
                    mma_bf16(acc[t][j], ah[t], &bh[2 * jj]);
                    mma_bf16(acc[t][j], ah[t], &bl[2 * jj]);
                    mma_bf16(acc[t][j], al[t], &bh[2 * jj]);
                }
        }

        if (kt + 2 < nkt) {
            uint32_t st2 = sb + (uint32_t)((kt + 2) % 3) * 16384u;
            int ko = (kt + 2) * 16;
            cpasync16(st2 + ldst,          gA_h + ko);
            cpasync16(st2 + 4096u + ldst,  gA_l + ko);
            cpasync16(st2 + 8192u + ldst,  gB_h + ko);
            cpasync16(st2 + 12288u + ldst, gB_l + ko);
            CP_COMMIT();
        }
    }

    // ---- RoPE epilogue (proj GEMM: Q,K head columns only) ----
    if (doRope && (n0 + wn * 64) < 1280) {
#pragma unroll
        for (int j = 0; j < 4; j++) {
#pragma unroll
            for (int e = 0; e < 2; e++) {
                int d = j * 8 + 2 * (lane & 3) + e;
                float invf = expf(-(float)(2 * d) * (9.210340371976184f / 64.f));
#pragma unroll
                for (int mt = 0; mt < 2; mt++) {
#pragma unroll
                    for (int rh = 0; rh < 2; rh++) {
                        int trow = m0 + wm * 32 + mt * 16 + (lane >> 2) + rh * 8;
                        float sn, cs;
                        sincosf((float)trow * invf, &sn, &cs);
                        int k = 2 * rh + e;
                        float a = acc[mt][j][k], b = acc[mt][j + 4][k];
                        acc[mt][j][k]     = a * cs - b * sn;
                        acc[mt][j + 4][k] = b * cs + a * sn;
                    }
                }
            }
        }
    }

#pragma unroll
    for (int t = 0; t < 2; t++) {
        int r0 = m0 + wm * 32 + t * 16 + (lane >> 2);
#pragma unroll
        for (int j = 0; j < 8; j++) {
            int col = n0 + wn * 64 + j * 8 + 2 * (lane & 3);
            *reinterpret_cast<float2*>(C + (size_t)r0 * N + col) = make_float2(acc[t][j][0], acc[t][j][1]);
            *reinterpret_cast<float2*>(C + (size_t)(r0 + 8) * N + col) = make_float2(acc[t][j][2], acc[t][j][3]);
        }
    }
}

// ---------------- per-head scan (warp-shuffle) ----------------
__global__ __launch_bounds__(256) void scan_kernel(
    const float* __restrict__ P, const float* __restrict__ bg,
    float* __restrict__ D, float* __restrict__ L)
{
    int h = blockIdx.x, tid = threadIdx.x, lane = tid & 31, wid = tid >> 5;
    float b = bg[h];
    float vals[8];
    float run = 0.f;
#pragma unroll
    for (int i = 0; i < 8; i++) {
        int t = tid * 8 + i;
        float gg = P[(size_t)t * PSTR + GOFF + h] + b;
        run += log_sigmoid_f(gg);
        vals[i] = run;
        L[h * T_SEQ + t] = log_sigmoid_f(-gg);
    }
    float x = run;
#pragma unroll
    for (int off = 1; off < 32; off <<= 1) {
        float y = __shfl_up_sync(0xffffffff, x, off);
        if (lane >= off) x += y;
    }
    __shared__ float wsum[8];
    if (lane == 31) wsum[wid] = x;
    __syncthreads();
    float woff = 0.f;
#pragma unroll
    for (int w = 0; w < 8; w++) if (w < wid) woff += wsum[w];
    float excl = x - run + woff;
#pragma unroll
    for (int i = 0; i < 8; i++) D[h * T_SEQ + tid * 8 + i] = vals[i] + excl;
}

// ---------------- fused attention (register-P) ----------------
#define OFF_Q  0u
#define OFF_K  16384u
#define OFF_V  32768u
#define OFF_S  49152u
#define SSTR   132
#define OFF_SC (49152u + 64u * SSTR * 4u)

__device__ __forceinline__ void pv_mma(
    uint32_t sbV, uint32_t pah[2][4], uint32_t pal[2][4],
    float (*oacc)[4], int wn, int lane)
{
#pragma unroll
    for (int u = 0; u < 2; u++) {
        int vrow = wn * 32 + u * 16 + (lane & 15);
        uint32_t vb = sbV + (uint32_t)vrow * 128u;
#pragma unroll
        for (int gg = 0; gg < 4; gg++) {
            int cch = 2 * gg + (lane >> 4);
            uint32_t vh[4], vl[4];
            ldsm4t(vh, vb + (uint32_t)((cch ^ (vrow & 7)) * 16));
            ldsm4t(vl, vb + 8192u + (uint32_t)((cch ^ (vrow & 7)) * 16));
#pragma unroll
            for (int jj = 0; jj < 2; jj++) {
                int j = gg * 2 + jj;
                mma_bf16(oacc[j], pah[u], &vh[2 * jj]);
                mma_bf16(oacc[j], pah[u], &vl[2 * jj]);
                mma_bf16(oacc[j], pal[u], &vh[2 * jj]);
            }
        }
    }
}

__global__ __launch_bounds__(256, 2) void attn_fused(
    const float* __restrict__ P, const float* __restrict__ D,
    const float* __restrict__ L, float* __restrict__ Y)
{
    extern __shared__ char smc[];
    uint32_t sb = cvta_smem(smc);
    float* smS  = reinterpret_cast<float*>(smc + OFF_S);
    float* Dq   = reinterpret_cast<float*>(smc + OFF_SC);
    float* rowE = Dq + 64;
    float* Ds   = rowE + 64;
    float* Ls   = Ds + 64;
    float* colE = Ls + 64;

    int qt = blockIdx.x, h = blockIdx.y;
    int kvh = h >> 2;
    int tid = threadIdx.x, lane = tid & 31, warp = tid >> 5;
    int wm = warp & 3, wn = warp >> 2;
    int t0 = qt * 64;
    int w0 = (t0 / WINSZ) * WINSZ;
    int wt0 = w0 / 64;
    int nk = t0 - w0 + 64;

    load_split_tile(P + (size_t)t0 * PSTR + h * DHD, sb + OFF_Q, sb + OFF_Q + 8192u, tid);
    if (tid < 64) Dq[tid] = D[h * T_SEQ + t0 + tid];
    __syncthreads();
    float dq0 = Dq[0];
    if (tid < 64) rowE[tid] = expf(Dq[tid] - dq0);

    int fr0 = wm * 16 + (lane >> 2);
    int fcb = wn * 32 + 2 * (lane & 3);

    float oacc[8][4] = {};

    for (int st = qt; st >= 0; --st) {
        int s0 = st * 64;
        bool inwin = (st >= wt0);
        if (!inwin) {
            float dend = D[h * T_SEQ + s0 + 63];
            if (dq0 - dend < -88.f) break;
        }
        __syncthreads();

        load_split_tile(P + (size_t)s0 * PSTR + KOFF + kvh * DHD, sb + OFF_K, sb + OFF_K + 8192u, tid);
        load_split_tile(P + (size_t)s0 * PSTR + VOFF + kvh * DHD, sb + OFF_V, sb + OFF_V + 8192u, tid);
        if (tid < 64) {
            float ds = D[h * T_SEQ + s0 + tid];
            float ls = L[h * T_SEQ + s0 + tid];
            Ds[tid] = ds; Ls[tid] = ls;
            colE[tid] = expf(dq0 - ds + ls);
        }
        __syncthreads();

        float sacc[4][4] = {};
        {
            int arow = wm * 16 + (lane & 15);
            int asel = lane >> 4;
            int nrow = wn * 32 + (lane & 7) + ((lane >> 4) << 3);
            int bsel = (lane >> 3) & 1;
#pragma unroll
            for (int ks = 0; ks < 4; ks++) {
                uint32_t ah[4], al[4];
                uint32_t abase = sb + OFF_Q + (uint32_t)arow * 128u;
                ldsm4(ah, abase + (uint32_t)(((2 * ks + asel) ^ (arow & 7)) * 16));
                ldsm4(al, abase + 8192u + (uint32_t)(((2 * ks + asel) ^ (arow & 7)) * 16));
                uint32_t bh[2][4], bl[2][4];
#pragma unroll
                for (int g = 0; g < 2; g++) {
                    int r = nrow + g * 16;
                    uint32_t bbase = sb + OFF_K + (uint32_t)r * 128u;
                    ldsm4(bh[g], bbase + (uint32_t)(((2 * ks + bsel) ^ (r & 7)) * 16));
                    ldsm4(bl[g], bbase + 8192u + (uint32_t)(((2 * ks + bsel) ^ (r & 7)) * 16));
                }
#pragma unroll
                for (int j = 0; j < 4; j++) {
                    const uint32_t* b2h = &bh[j >> 1][2 * (j & 1)];
                    const uint32_t* b2l = &bl[j >> 1][2 * (j & 1)];
                    mma_bf16(sacc[j], ah, b2h);
                    mma_bf16(sacc[j], ah, b2l);
                    mma_bf16(sacc[j], al, b2h);
                }
            }
        }

        uint32_t pah[2][4], pal[2][4];
        {
            int colbase = s0 - w0;
#pragma unroll
            for (int j = 0; j < 4; j++) {
                int cj = fcb + 8 * j;
#pragma unroll
                for (int half = 0; half < 2; half++) {
                    int r = fr0 + half * 8;
                    float v0 = sacc[j][2 * half], v1 = sacc[j][2 * half + 1];
                    if (inwin) {
                        float l0 = (s0 + cj     <= t0 + r) ? v0 * 0.125f : neg_inf();
                        float l1 = (s0 + cj + 1 <= t0 + r) ? v1 * 0.125f : neg_inf();
                        *reinterpret_cast<float2*>(&smS[r * SSTR + colbase + cj]) = make_float2(l0, l1);
                    }
                    float p0, p1;
                    if (st == qt) {
                        p0 = (cj     <= r) ? v0 * expf(Dq[r] - Ds[cj] + Ls[cj]) : 0.f;
                        p1 = (cj + 1 <= r) ? v1 * expf(Dq[r] - Ds[cj + 1] + Ls[cj + 1]) : 0.f;
                    } else {
                        float re = rowE[r];
                        p0 = v0 * (re * colE[cj]);
                        p1 = v1 * (re * colE[cj + 1]);
                    }
                    float h0 = __bfloat162float(__float2bfloat16_rn(p0));
                    float h1 = __bfloat162float(__float2bfloat16_rn(p1));
                    int u = j >> 1, ri = (j & 1) * 2 + half;
                    pah[u][ri] = pack2bf(h0, h1);
                    pal[u][ri] = pack2bf(p0 - h0, p1 - h1);
                }
            }
        }

        pv_mma(sb + OFF_V, pah, pal, oacc, wn, lane);
    }

    __syncthreads();
    {
        int r = tid >> 2, g = tid & 3;
        float m = neg_inf();
        for (int c = g; c < nk; c += 4) m = fmaxf(m, smS[r * SSTR + c]);
        m = fmaxf(m, __shfl_xor_sync(0xffffffff, m, 1));
        m = fmaxf(m, __shfl_xor_sync(0xffffffff, m, 2));
        float sum = 0.f;
        for (int c = g; c < nk; c += 4) {
            float e = expf(smS[r * SSTR + c] - m);
            smS[r * SSTR + c] = e;
            sum += e;
        }
        sum += __shfl_xor_sync(0xffffffff, sum, 1);
        sum += __shfl_xor_sync(0xffffffff, sum, 2);
        float inv = 1.f / sum;
        for (int c = g; c < nk; c += 4) smS[r * SSTR + c] *= inv;
    }

    for (int kh = 0; kh < (nk >> 6); kh++) {
        __syncthreads();
        load_split_tile(P + (size_t)(w0 + kh * 64) * PSTR + VOFF + kvh * DHD, sb + OFF_V, sb + OFF_V + 8192u, tid);
        __syncthreads();
        uint32_t pah[2][4], pal[2][4];
#pragma unroll
        for (int u = 0; u < 2; u++) {
            int bc = kh * 64 + wn * 32 + u * 16 + 2 * (lane & 3);
            float2 f0 = *reinterpret_cast<const float2*>(&smS[fr0 * SSTR + bc]);
            float2 f1 = *reinterpret_cast<const float2*>(&smS[(fr0 + 8) * SSTR + bc]);
            float2 f2 = *reinterpret_cast<const float2*>(&smS[fr0 * SSTR + bc + 8]);
            float2 f3 = *reinterpret_cast<const float2*>(&smS[(fr0 + 8) * SSTR + bc + 8]);
            float h, h2;
            h = __bfloat162float(__float2bfloat16_rn(f0.x));
            h2 = __bfloat162float(__float2bfloat16_rn(f0.y));
            pah[u][0] = pack2bf(h, h2); pal[u][0] = pack2bf(f0.x - h, f0.y - h2);
            h = __bfloat162float(__float2bfloat16_rn(f1.x));
            h2 = __bfloat162float(__float2bfloat16_rn(f1.y));
            pah[u][1] = pack2bf(h, h2); pal[u][1] = pack2bf(f1.x - h, f1.y - h2);
            h = __bfloat162float(__float2bfloat16_rn(f2.x));
            h2 = __bfloat162float(__float2bfloat16_rn(f2.y));
            pah[u][2] = pack2bf(h, h2); pal[u][2] = pack2bf(f2.x - h, f2.y - h2);
            h = __bfloat162float(__float2bfloat16_rn(f3.x));
            h2 = __bfloat162float(__float2bfloat16_rn(f3.y));
            pah[u][3] = pack2bf(h, h2); pal[u][3] = pack2bf(f3.x - h, f3.y - h2);
        }
        pv_mma(sb + OFF_V, pah, pal, oacc, wn, lane);
    }

    __syncthreads();
    float* redb = reinterpret_cast<float*>(smc + OFF_K);
    if (wn == 1) {
        int base = (wm * 32 + lane) * 32;
#pragma unroll
        for (int j = 0; j < 8; j++)
#pragma unroll
            for (int k = 0; k < 4; k++) redb[base + j * 4 + k] = oacc[j][k];
    }
    __syncthreads();
    if (wn == 0) {
        int base = (wm * 32 + lane) * 32;
#pragma unroll
        for (int j = 0; j < 8; j++) {
            float o0 = oacc[j][0] + redb[base + j * 4 + 0];
            float o1 = oacc[j][1] + redb[base + j * 4 + 1];
            float o2 = oacc[j][2] + redb[base + j * 4 + 2];
            float o3 = oacc[j][3] + redb[base + j * 4 + 3];
            int col = h * DHD + j * 8 + 2 * (lane & 3);
            *reinterpret_cast<float2*>(Y + (size_t)(t0 + fr0) * C_DIM + col) = make_float2(o0, o1);
            *reinterpret_cast<float2*>(Y + (size_t)(t0 + fr0 + 8) * C_DIM + col) = make_float2(o2, o3);
        }
    }
}

// ---------------- launch ----------------
extern "C" void kernel_launch(void* const* d_in, const int* in_sizes, int n_in,
                              void* d_out, int out_size)
{
    (void)in_sizes; (void)n_in; (void)out_size;
    const float* x    = (const float*)d_in[0];
    const float* Wq   = (const float*)d_in[1];
    const float* Wk   = (const float*)d_in[2];
    const float* Wv   = (const float*)d_in[3];
    const float* Wc   = (const float*)d_in[4];
    const float* Wg   = (const float*)d_in[5];
    const float* bg   = (const float*)d_in[6];
    const float* rmsw = (const float*)d_in[7];
    float* out = (float*)d_out;

    float *P, *D, *L, *Y;
    __nv_bfloat16 *Xh, *Xl, *Yh, *Yl, *Wph, *Wpl, *Wch, *Wcl;
    cudaGetSymbolAddress((void**)&P, g_P);
    cudaGetSymbolAddress((void**)&D, g_D);
    cudaGetSymbolAddress((void**)&L, g_L);
    cudaGetSymbolAddress((void**)&Y, g_Y);
    cudaGetSymbolAddress((void**)&Xh, g_Xh);
    cudaGetSymbolAddress((void**)&Xl, g_Xl);
    cudaGetSymbolAddress((void**)&Yh, g_Yh);
    cudaGetSymbolAddress((void**)&Yl, g_Yl);
    cudaGetSymbolAddress((void**)&Wph, g_Wp_h);
    cudaGetSymbolAddress((void**)&Wpl, g_Wp_l);
    cudaGetSymbolAddress((void**)&Wch, g_Wc_h);
    cudaGetSymbolAddress((void**)&Wcl, g_Wc_l);

    transpose_split_all<<<dim3(32, 32, 5), 256>>>(Wq, Wk, Wv, Wc, Wg, rmsw, Wph, Wpl, Wch, Wcl);
    split_act<<<T_SEQ, 256>>>(x, Xh, Xl, 0);

    size_t smemG = 3 * 16384;
    cudaFuncSetAttribute(gemm_bf16, cudaFuncAttributeMaxDynamicSharedMemorySize, (int)smemG);
    gemm_bf16<<<dim3(PSTR / 128, T_SEQ / 128), 256, smemG>>>(Xh, Xl, Wph, Wpl, P, T_SEQ, PSTR, C_DIM, 1);

    scan_kernel<<<NH, 256>>>(P, bg, D, L);

    size_t smemA = OFF_SC + 6 * 64 * sizeof(float);
    cudaFuncSetAttribute(attn_fused, cudaFuncAttributeMaxDynamicSharedMemorySize, (int)smemA);
    attn_fused<<<dim3(T_SEQ / 64, NH), 256, smemA>>>(P, D, L, Y);

    split_act<<<T_SEQ, 256>>>(Y, Yh, Yl, 1);
    gemm_bf16<<<dim3(C_DIM / 128, T_SEQ / 128), 256, smemG>>>(Yh, Yl, Wch, Wcl, out, T_SEQ, C_DIM, C_DIM, 0);
}